// round 12
// baseline (speedup 1.0000x reference)
#include <cuda_runtime.h>
#include <cuda_fp16.h>
#include <math.h>

// ---------------------------------------------------------------------------
// Swin: B=16, H=W=64, DIM=256, HEADS=8, HD=32, WS=8, N=64, NW=64, MLP_H=1024
// fp16 datapath, fp32 accumulate, fp32 residual stream.
// ---------------------------------------------------------------------------

#define NTOK 65536

static __device__ __half g_xw  [NTOK * 256];
static __device__ __half g_qkv [NTOK * 768];
static __device__ __half g_attn[NTOK * 256];
static __device__ __half g_h2  [NTOK * 256];
static __device__ __half g_mlp [NTOK * 1024];
static __device__ __half g_proj[NTOK * 256];
static __device__ __half g_wt  [2 * 786432];

__device__ __forceinline__ unsigned pack_h(float x, float y) {
    __half2 h = __floats2half2_rn(x, y);
    return *(unsigned*)&h;
}

// ---------------------------------------------------------------------------
// Merged weight convert+transpose for BOTH blocks: W[K][N] fp32 -> Wt[N][K] fp16
// ---------------------------------------------------------------------------
struct WtArgs {
    const float* w[8];
    __half*      o[8];
};

__global__ void wt_all_kernel(WtArgs args)
{
    __shared__ float tile[32][33];
    int b = blockIdx.x;
    int blk = b >= 768;
    b -= blk * 768;
    const float* W; __half* Wt; int K, N, nb, sel;
    if (b < 192)      { sel = 0; K = 256;  N = 768;  nb = 24; }
    else if (b < 256) { b -= 192; sel = 1; K = 256;  N = 256;  nb = 8; }
    else if (b < 512) { b -= 256; sel = 2; K = 256;  N = 1024; nb = 32; }
    else              { b -= 512; sel = 3; K = 1024; N = 256;  nb = 8; }
    W  = args.w[blk * 4 + sel];
    Wt = args.o[blk * 4 + sel];
    int n0 = (b % nb) << 5, k0 = (b / nb) << 5;
    int tx = threadIdx.x, ty = threadIdx.y;
    #pragma unroll
    for (int i = 0; i < 4; i++)
        tile[ty + i * 8][tx] = W[(size_t)(k0 + ty + i * 8) * N + n0 + tx];
    __syncthreads();
    #pragma unroll
    for (int i = 0; i < 4; i++)
        Wt[(size_t)(n0 + ty + i * 8) * K + k0 + tx] =
            __float2half_rn(tile[tx][ty + i * 8]);
}

// ---------------------------------------------------------------------------
// LayerNorm (+shift + window partition), fp32 in -> fp16 out. One warp/row.
// ---------------------------------------------------------------------------
__global__ void ln_kernel(const float* __restrict__ x,
                          const float* __restrict__ gamma,
                          const float* __restrict__ beta,
                          __half* __restrict__ out,
                          int shift)
{
    int gw   = (blockIdx.x * blockDim.x + threadIdx.x) >> 5;
    int lane = threadIdx.x & 31;
    if (gw >= NTOK) return;

    int win = gw >> 6, n = gw & 63;
    int b  = win >> 6, wi = win & 63;
    int h  = (((wi >> 3) << 3) + (n >> 3) + shift) & 63;
    int w  = (((wi & 7)  << 3) + (n & 7)  + shift) & 63;
    int src = (b << 12) + (h << 6) + w;

    const float4* xr = (const float4*)x + (size_t)src * 64;
    float4 v0 = xr[lane];
    float4 v1 = xr[lane + 32];

    float s = v0.x + v0.y + v0.z + v0.w + v1.x + v1.y + v1.z + v1.w;
    #pragma unroll
    for (int o = 16; o; o >>= 1) s += __shfl_xor_sync(0xffffffffu, s, o);
    float mean = s * (1.0f / 256.0f);

    float a, ss = 0.f;
    a = v0.x - mean; ss += a * a;  a = v0.y - mean; ss += a * a;
    a = v0.z - mean; ss += a * a;  a = v0.w - mean; ss += a * a;
    a = v1.x - mean; ss += a * a;  a = v1.y - mean; ss += a * a;
    a = v1.z - mean; ss += a * a;  a = v1.w - mean; ss += a * a;
    #pragma unroll
    for (int o = 16; o; o >>= 1) ss += __shfl_xor_sync(0xffffffffu, ss, o);
    float rstd = rsqrtf(ss * (1.0f / 256.0f) + 1e-5f);

    const float4* g4 = (const float4*)gamma;
    const float4* b4 = (const float4*)beta;
    float4 g0 = g4[lane], g1 = g4[lane + 32];
    float4 c0 = b4[lane], c1 = b4[lane + 32];

    unsigned* o32 = (unsigned*)(out + (size_t)gw * 256);
    uint2 r0, r1;
    r0.x = pack_h((v0.x - mean) * rstd * g0.x + c0.x,
                  (v0.y - mean) * rstd * g0.y + c0.y);
    r0.y = pack_h((v0.z - mean) * rstd * g0.z + c0.z,
                  (v0.w - mean) * rstd * g0.w + c0.w);
    r1.x = pack_h((v1.x - mean) * rstd * g1.x + c1.x,
                  (v1.y - mean) * rstd * g1.y + c1.y);
    r1.y = pack_h((v1.z - mean) * rstd * g1.z + c1.z,
                  (v1.w - mean) * rstd * g1.w + c1.w);
    *(uint2*)(o32 + lane * 2)      = r0;
    *(uint2*)(o32 + 64 + lane * 2) = r1;
}

// ---------------------------------------------------------------------------
// Fused window-reverse + un-shift + residual + LayerNorm2.
// ---------------------------------------------------------------------------
__global__ void rev_ln_kernel(const __half* __restrict__ proj,
                              const float* __restrict__ x_src,
                              float* __restrict__ x_dst,
                              const float* __restrict__ gamma,
                              const float* __restrict__ beta,
                              __half* __restrict__ h2,
                              int shift)
{
    int gw   = (blockIdx.x * blockDim.x + threadIdx.x) >> 5;
    int lane = threadIdx.x & 31;
    if (gw >= NTOK) return;

    int b = gw >> 12, h = (gw >> 6) & 63, w = gw & 63;
    int hh = (h - shift) & 63, ww = (w - shift) & 63;
    int row = ((b << 6) + ((hh >> 3) << 3) + (ww >> 3)) * 64
            + ((hh & 7) << 3) + (ww & 7);

    const __half2* pr = (const __half2*)(proj + (size_t)row * 256);
    const float4* xr = (const float4*)x_src + (size_t)gw * 64;
    float4 v0 = xr[lane],      v1 = xr[lane + 32];
    __half2 pa = pr[lane * 2],      pb = pr[lane * 2 + 1];
    __half2 pc = pr[64 + lane * 2], pd = pr[64 + lane * 2 + 1];
    float2 fa = __half22float2(pa), fb = __half22float2(pb);
    float2 fc = __half22float2(pc), fd = __half22float2(pd);
    v0.x += fa.x; v0.y += fa.y; v0.z += fb.x; v0.w += fb.y;
    v1.x += fc.x; v1.y += fc.y; v1.z += fd.x; v1.w += fd.y;

    float4* xo = (float4*)x_dst + (size_t)gw * 64;
    xo[lane]      = v0;
    xo[lane + 32] = v1;

    float s = v0.x + v0.y + v0.z + v0.w + v1.x + v1.y + v1.z + v1.w;
    #pragma unroll
    for (int o = 16; o; o >>= 1) s += __shfl_xor_sync(0xffffffffu, s, o);
    float mean = s * (1.0f / 256.0f);

    float a, ss = 0.f;
    a = v0.x - mean; ss += a * a;  a = v0.y - mean; ss += a * a;
    a = v0.z - mean; ss += a * a;  a = v0.w - mean; ss += a * a;
    a = v1.x - mean; ss += a * a;  a = v1.y - mean; ss += a * a;
    a = v1.z - mean; ss += a * a;  a = v1.w - mean; ss += a * a;
    #pragma unroll
    for (int o = 16; o; o >>= 1) ss += __shfl_xor_sync(0xffffffffu, ss, o);
    float rstd = rsqrtf(ss * (1.0f / 256.0f) + 1e-5f);

    const float4* g4 = (const float4*)gamma;
    const float4* b4 = (const float4*)beta;
    float4 g0 = g4[lane], g1 = g4[lane + 32];
    float4 c0 = b4[lane], c1 = b4[lane + 32];

    unsigned* o32 = (unsigned*)(h2 + (size_t)gw * 256);
    uint2 r0, r1;
    r0.x = pack_h((v0.x - mean) * rstd * g0.x + c0.x,
                  (v0.y - mean) * rstd * g0.y + c0.y);
    r0.y = pack_h((v0.z - mean) * rstd * g0.z + c0.z,
                  (v0.w - mean) * rstd * g0.w + c0.w);
    r1.x = pack_h((v1.x - mean) * rstd * g1.x + c1.x,
                  (v1.y - mean) * rstd * g1.y + c1.y);
    r1.y = pack_h((v1.z - mean) * rstd * g1.z + c1.z,
                  (v1.w - mean) * rstd * g1.w + c1.w);
    *(uint2*)(o32 + lane * 2)      = r0;
    *(uint2*)(o32 + 64 + lane * 2) = r1;
}

// ---------------------------------------------------------------------------
// fp16 tensor-core GEMM, WIDE-N tile: 128x256x32, 8 warps (4m x 2n),
// warp tile 32x128, m16n8k16, 3-stage cp.async, ldmatrix.x4 loads.
// Halves A traffic; doubles per-warp mma ILP.
// ---------------------------------------------------------------------------
#define HSTRIDE 40
#define ASTG (128 * HSTRIDE)           // halves, A per stage
#define BSTG (256 * HSTRIDE)           // halves, B per stage
#define STAGE_H (ASTG + BSTG)
#define GEMM_SMEM_B (3 * STAGE_H * 2)  // 92160 bytes

__device__ __forceinline__ void cp16(void* s, const void* g) {
    unsigned sa = (unsigned)__cvta_generic_to_shared(s);
    asm volatile("cp.async.cg.shared.global [%0], [%1], 16;" :: "r"(sa), "l"(g));
}

__device__ __forceinline__ void ldm4(unsigned& r0, unsigned& r1,
                                     unsigned& r2, unsigned& r3, unsigned addr) {
    asm volatile("ldmatrix.sync.aligned.m8n8.x4.shared.b16 {%0,%1,%2,%3}, [%4];"
                 : "=r"(r0), "=r"(r1), "=r"(r2), "=r"(r3) : "r"(addr));
}

__device__ __forceinline__ void ldm2t(unsigned& r0, unsigned& r1, unsigned addr) {
    asm volatile("ldmatrix.sync.aligned.m8n8.x2.trans.shared.b16 {%0,%1}, [%2];"
                 : "=r"(r0), "=r"(r1) : "r"(addr));
}

__global__ void __launch_bounds__(256, 1)
h_gemm_kernel(const __half* __restrict__ A,
              const __half* __restrict__ Bt,
              const float* __restrict__ bias,
              const float* __restrict__ R,
              void* __restrict__ Cv,
              int N, int K, int act, int out_h16)
{
    extern __shared__ __half smem[];
    __half* As = smem;                     // 3 stages of A then 3 of B
    __half* Bs = smem + 3 * ASTG;

    int tid  = threadIdx.x;
    int bm   = blockIdx.y << 7;
    int bn   = blockIdx.x << 8;            // 256-wide tiles
    int wid  = tid >> 5, lane = tid & 31;
    int wm   = (wid & 3) << 5;
    int wn   = (wid >> 2) << 7;            // 0 / 128
    int g    = lane >> 2, t = lane & 3;

    float acc[2][16][4];
    #pragma unroll
    for (int mi = 0; mi < 2; mi++)
        #pragma unroll
        for (int ni = 0; ni < 16; ni++)
            #pragma unroll
            for (int c = 0; c < 4; c++) acc[mi][ni][c] = 0.f;

    int r4 = tid >> 2;          // 0..63
    int c4 = (tid & 3) << 3;    // 0,8,16,24 halves
    int iters = K >> 5;

    unsigned as_u = (unsigned)__cvta_generic_to_shared(As);
    unsigned bs_u = (unsigned)__cvta_generic_to_shared(Bs);
    int a_off = (wm + (lane & 15)) * HSTRIDE + ((lane >> 4) << 3);
    int b_off = (wn + ((lane >> 4) << 3) + (lane & 7)) * HSTRIDE
              + (((lane >> 3) & 1) << 3);

    // A: 128 rows x 32 halves = 512 cp16 (2/thread); B: 256 rows = 1024 (4/thread)
    #define LOAD_STAGE(si, kb)                                                  \
    {                                                                           \
        __half* as = As + (si) * ASTG;                                          \
        __half* bs = Bs + (si) * BSTG;                                          \
        cp16(as + r4 * HSTRIDE + c4,                                            \
             A + (size_t)(bm + r4) * K + (kb) + c4);                            \
        cp16(as + (r4 + 64) * HSTRIDE + c4,                                     \
             A + (size_t)(bm + r4 + 64) * K + (kb) + c4);                       \
        _Pragma("unroll")                                                       \
        for (int u = 0; u < 4; u++)                                             \
            cp16(bs + (r4 + (u << 6)) * HSTRIDE + c4,                           \
                 Bt + (size_t)(bn + r4 + (u << 6)) * K + (kb) + c4);            \
        asm volatile("cp.async.commit_group;");                                 \
    }

    LOAD_STAGE(0, 0)
    LOAD_STAGE(1, 32)

    for (int i = 0; i < iters; i++) {
        if (i + 2 <= iters) {
            asm volatile("cp.async.wait_group 1;");
        } else {
            asm volatile("cp.async.wait_group 0;");
        }
        __syncthreads();   // all warps done with stage (i-1) -> slot (i+2)%3 free

        if (i + 2 < iters) LOAD_STAGE((i + 2) % 3, (i + 2) << 5)

        unsigned abase = as_u + ((i % 3) * ASTG) * 2;
        unsigned bbase = bs_u + ((i % 3) * BSTG) * 2;
        #pragma unroll
        for (int kk = 0; kk < 2; kk++) {
            int k0 = kk << 4;
            unsigned af[2][4], bf[16][2];
            #pragma unroll
            for (int mi = 0; mi < 2; mi++)
                ldm4(af[mi][0], af[mi][1], af[mi][2], af[mi][3],
                     abase + (a_off + (mi << 4) * HSTRIDE + k0) * 2);
            #pragma unroll
            for (int p = 0; p < 8; p++)
                ldm4(bf[2 * p][0], bf[2 * p][1], bf[2 * p + 1][0], bf[2 * p + 1][1],
                     bbase + (b_off + (p << 4) * HSTRIDE + k0) * 2);
            #pragma unroll
            for (int mi = 0; mi < 2; mi++)
                #pragma unroll
                for (int ni = 0; ni < 16; ni++) {
                    asm("mma.sync.aligned.m16n8k16.row.col.f32.f16.f16.f32 "
                        "{%0,%1,%2,%3}, {%4,%5,%6,%7}, {%8,%9}, {%0,%1,%2,%3};"
                        : "+f"(acc[mi][ni][0]), "+f"(acc[mi][ni][1]),
                          "+f"(acc[mi][ni][2]), "+f"(acc[mi][ni][3])
                        : "r"(af[mi][0]), "r"(af[mi][1]), "r"(af[mi][2]), "r"(af[mi][3]),
                          "r"(bf[ni][0]), "r"(bf[ni][1]));
                }
        }
    }

    #pragma unroll
    for (int mi = 0; mi < 2; mi++) {
        int row0 = bm + wm + (mi << 4) + g;
        #pragma unroll
        for (int ni = 0; ni < 16; ni++) {
            int col = bn + wn + (ni << 3) + (t << 1);
            float2 bb = *(const float2*)(bias + col);
            float2 u, v;
            u.x = acc[mi][ni][0] + bb.x;
            u.y = acc[mi][ni][1] + bb.y;
            v.x = acc[mi][ni][2] + bb.x;
            v.y = acc[mi][ni][3] + bb.y;
            if (act) {
                u.x = 0.5f * u.x * (1.f + erff(u.x * 0.70710678118654752f));
                u.y = 0.5f * u.y * (1.f + erff(u.y * 0.70710678118654752f));
                v.x = 0.5f * v.x * (1.f + erff(v.x * 0.70710678118654752f));
                v.y = 0.5f * v.y * (1.f + erff(v.y * 0.70710678118654752f));
            }
            size_t o0 = (size_t)row0 * N + col;
            size_t o1 = (size_t)(row0 + 8) * N + col;
            if (out_h16) {
                unsigned* C = (unsigned*)Cv;
                C[o0 >> 1] = pack_h(u.x, u.y);
                C[o1 >> 1] = pack_h(v.x, v.y);
            } else {
                float* C = (float*)Cv;
                if (R) {
                    float2 r0 = *(const float2*)(R + o0);
                    float2 r1 = *(const float2*)(R + o1);
                    u.x += r0.x; u.y += r0.y; v.x += r1.x; v.y += r1.y;
                }
                *(float2*)(C + o0) = u;
                *(float2*)(C + o1) = v;
            }
        }
    }
}

// ---------------------------------------------------------------------------
// fp16 tensor-core window attention: 2 windows (same head) per 256-thread CTA.
// Q staged through ps (reused for P); all fragments via ldmatrix. (R11)
// ---------------------------------------------------------------------------
__global__ void __launch_bounds__(256)
attn_tc_kernel(const __half* __restrict__ qkv,
               const float* __restrict__ rpb,
               __half* __restrict__ out,
               int masked)
{
    __shared__ __half ks[2][64][40];
    __shared__ __half vs[2][64][40];
    __shared__ __half ps[2][64][72];
    __shared__ float rb[232];

    const float SCALE = 0.17677669529663687f;

    int idx  = blockIdx.x;
    int head = idx & 7;
    int wp   = idx >> 3;
    int tid  = threadIdx.x;
    int warp = tid >> 5, lane = tid & 31;
    int g = lane >> 2, t = lane & 3;

    {
        int sw   = tid >> 7;
        int stid = tid & 127;
        int tok  = stid >> 1;
        int half = (stid & 1) << 4;
        const __half* bq = qkv + (size_t)((wp * 2 + sw) * 64 + tok) * 768 + head * 32 + half;
        uint4 qa = *(const uint4*)(bq);
        uint4 qb = *(const uint4*)(bq + 8);
        *(uint4*)&ps[sw][tok][half]     = qa;
        *(uint4*)&ps[sw][tok][half + 8] = qb;
        uint4 ka = *(const uint4*)(bq + 256);
        uint4 kb = *(const uint4*)(bq + 264);
        *(uint4*)&ks[sw][tok][half]     = ka;
        *(uint4*)&ks[sw][tok][half + 8] = kb;
        uint4 va = *(const uint4*)(bq + 512);
        uint4 vb = *(const uint4*)(bq + 520);
        *(uint4*)&vs[sw][tok][half]     = va;
        *(uint4*)&vs[sw][tok][half + 8] = vb;
    }
    for (int r = tid; r < 225; r += 256) rb[r] = rpb[r * 8 + head];
    __syncthreads();

    int wloc = warp >> 2;
    int win  = wp * 2 + wloc;
    int wm   = (warp & 3) << 4;
    int i_lo = wm + g, i_hi = i_lo + 8;

    unsigned ks_u = (unsigned)__cvta_generic_to_shared(&ks[wloc][0][0]);
    unsigned vs_u = (unsigned)__cvta_generic_to_shared(&vs[wloc][0][0]);
    unsigned ps_u = (unsigned)__cvta_generic_to_shared(&ps[wloc][0][0]);
    int b_off = (((lane >> 4) << 3) + (lane & 7)) * 40 + (((lane >> 3) & 1) << 3);
    int a_off = (wm + (lane & 15)) * 72 + ((lane >> 4) << 3);

    float sacc[8][4];
    #pragma unroll
    for (int ni = 0; ni < 8; ni++)
        #pragma unroll
        for (int c = 0; c < 4; c++) sacc[ni][c] = 0.f;

    #pragma unroll
    for (int kk = 0; kk < 2; kk++) {
        int k0 = kk << 4;
        unsigned qf[4];
        ldm4(qf[0], qf[1], qf[2], qf[3], ps_u + (a_off + k0) * 2);
        unsigned bf[8][2];
        #pragma unroll
        for (int p = 0; p < 4; p++)
            ldm4(bf[2 * p][0], bf[2 * p][1], bf[2 * p + 1][0], bf[2 * p + 1][1],
                 ks_u + (b_off + (p << 4) * 40 + k0) * 2);
        #pragma unroll
        for (int ni = 0; ni < 8; ni++) {
            asm("mma.sync.aligned.m16n8k16.row.col.f32.f16.f16.f32 "
                "{%0,%1,%2,%3}, {%4,%5,%6,%7}, {%8,%9}, {%0,%1,%2,%3};"
                : "+f"(sacc[ni][0]), "+f"(sacc[ni][1]),
                  "+f"(sacc[ni][2]), "+f"(sacc[ni][3])
                : "r"(qf[0]), "r"(qf[1]), "r"(qf[2]), "r"(qf[3]),
                  "r"(bf[ni][0]), "r"(bf[ni][1]));
        }
    }

    int yi0 = i_lo >> 3, xi0 = i_lo & 7;
    int yi1 = i_hi >> 3, xi1 = i_hi & 7;
    int wi = win & 63;
    int whbase = (wi >> 3) << 3;
    int wwbase = (wi & 7) << 3;
    int reg0 = 0, reg1 = 0;
    if (masked) {
        int h0 = whbase + yi0, w0 = wwbase + xi0;
        int h1 = whbase + yi1, w1 = wwbase + xi1;
        reg0 = ((h0 >= 56) + (h0 >= 60)) * 3 + (w0 >= 56) + (w0 >= 60);
        reg1 = ((h1 >= 56) + (h1 >= 60)) * 3 + (w1 >= 56) + (w1 >= 60);
    }
    #pragma unroll
    for (int ni = 0; ni < 8; ni++) {
        #pragma unroll
        for (int c = 0; c < 2; c++) {
            int j = (ni << 3) + (t << 1) + c;
            int yj = j >> 3, xj = j & 7;
            sacc[ni][c]     = sacc[ni][c]     * SCALE + rb[(yi0 - yj + 7) * 15 + (xi0 - xj + 7)];
            sacc[ni][2 + c] = sacc[ni][2 + c] * SCALE + rb[(yi1 - yj + 7) * 15 + (xi1 - xj + 7)];
            if (masked) {
                int hj = whbase + yj, wj = wwbase + xj;
                int regj = ((hj >= 56) + (hj >= 60)) * 3 + (wj >= 56) + (wj >= 60);
                if (regj != reg0) sacc[ni][c]     -= 100.f;
                if (regj != reg1) sacc[ni][2 + c] -= 100.f;
            }
        }
    }

    float mlo = -1e30f, mhi = -1e30f;
    #pragma unroll
    for (int ni = 0; ni < 8; ni++) {
        mlo = fmaxf(mlo, fmaxf(sacc[ni][0], sacc[ni][1]));
        mhi = fmaxf(mhi, fmaxf(sacc[ni][2], sacc[ni][3]));
    }
    mlo = fmaxf(mlo, __shfl_xor_sync(0xffffffffu, mlo, 1));
    mlo = fmaxf(mlo, __shfl_xor_sync(0xffffffffu, mlo, 2));
    mhi = fmaxf(mhi, __shfl_xor_sync(0xffffffffu, mhi, 1));
    mhi = fmaxf(mhi, __shfl_xor_sync(0xffffffffu, mhi, 2));

    float slo = 0.f, shi = 0.f;
    #pragma unroll
    for (int ni = 0; ni < 8; ni++) {
        sacc[ni][0] = __expf(sacc[ni][0] - mlo);
        sacc[ni][1] = __expf(sacc[ni][1] - mlo);
        sacc[ni][2] = __expf(sacc[ni][2] - mhi);
        sacc[ni][3] = __expf(sacc[ni][3] - mhi);
        slo += sacc[ni][0] + sacc[ni][1];
        shi += sacc[ni][2] + sacc[ni][3];
    }
    slo += __shfl_xor_sync(0xffffffffu, slo, 1);
    slo += __shfl_xor_sync(0xffffffffu, slo, 2);
    shi += __shfl_xor_sync(0xffffffffu, shi, 1);
    shi += __shfl_xor_sync(0xffffffffu, shi, 2);
    float inv_lo = 1.f / slo, inv_hi = 1.f / shi;

    #pragma unroll
    for (int ni = 0; ni < 8; ni++) {
        *(unsigned*)&ps[wloc][i_lo][(ni << 3) + (t << 1)] = pack_h(sacc[ni][0], sacc[ni][1]);
        *(unsigned*)&ps[wloc][i_hi][(ni << 3) + (t << 1)] = pack_h(sacc[ni][2], sacc[ni][3]);
    }
    __syncwarp();

    float oacc[4][4];
    #pragma unroll
    for (int ni = 0; ni < 4; ni++)
        #pragma unroll
        for (int c = 0; c < 4; c++) oacc[ni][c] = 0.f;

    #pragma unroll
    for (int kk = 0; kk < 4; kk++) {
        int k0 = kk << 4;
        unsigned af[4];
        ldm4(af[0], af[1], af[2], af[3], ps_u + (a_off + k0) * 2);
        #pragma unroll
        for (int ni = 0; ni < 4; ni++) {
            unsigned b0, b1;
            ldm2t(b0, b1, vs_u + ((k0 + (lane & 15)) * 40 + (ni << 3)) * 2);
            asm("mma.sync.aligned.m16n8k16.row.col.f32.f16.f16.f32 "
                "{%0,%1,%2,%3}, {%4,%5,%6,%7}, {%8,%9}, {%0,%1,%2,%3};"
                : "+f"(oacc[ni][0]), "+f"(oacc[ni][1]),
                  "+f"(oacc[ni][2]), "+f"(oacc[ni][3])
                : "r"(af[0]), "r"(af[1]), "r"(af[2]), "r"(af[3]),
                  "r"(b0), "r"(b1));
        }
    }

    __half* olo = out + (size_t)(win * 64 + i_lo) * 256 + head * 32;
    __half* ohi = out + (size_t)(win * 64 + i_hi) * 256 + head * 32;
    #pragma unroll
    for (int ni = 0; ni < 4; ni++) {
        int col = (ni << 3) + (t << 1);
        *(unsigned*)(olo + col) = pack_h(oacc[ni][0] * inv_lo, oacc[ni][1] * inv_lo);
        *(unsigned*)(ohi + col) = pack_h(oacc[ni][2] * inv_hi, oacc[ni][3] * inv_hi);
    }
}

// ---------------------------------------------------------------------------
extern "C" void kernel_launch(void* const* d_in, const int* in_sizes, int n_in,
                              void* d_out, int out_size)
{
    (void)in_sizes; (void)n_in; (void)out_size;

    __half *xw, *qkv, *attnb, *h2, *mlp, *wt, *proj;
    cudaGetSymbolAddress((void**)&xw,    g_xw);
    cudaGetSymbolAddress((void**)&qkv,   g_qkv);
    cudaGetSymbolAddress((void**)&attnb, g_attn);
    cudaGetSymbolAddress((void**)&h2,    g_h2);
    cudaGetSymbolAddress((void**)&mlp,   g_mlp);
    cudaGetSymbolAddress((void**)&proj,  g_proj);
    cudaGetSymbolAddress((void**)&wt,    g_wt);

    cudaFuncSetAttribute(h_gemm_kernel,
                         cudaFuncAttributeMaxDynamicSharedMemorySize, GEMM_SMEM_B);

    const float* x_in = (const float*)d_in[0];
    float* x = (float*)d_out;

    WtArgs wa;
    for (int blk = 0; blk < 2; blk++) {
        int base = 1 + 13 * blk;
        wa.w[blk * 4 + 0] = (const float*)d_in[base + 2];
        wa.w[blk * 4 + 1] = (const float*)d_in[base + 5];
        wa.w[blk * 4 + 2] = (const float*)d_in[base + 9];
        wa.w[blk * 4 + 3] = (const float*)d_in[base + 11];
        __half* wb = wt + blk * 786432;
        wa.o[blk * 4 + 0] = wb;
        wa.o[blk * 4 + 1] = wb + 196608;
        wa.o[blk * 4 + 2] = wb + 262144;
        wa.o[blk * 4 + 3] = wb + 524288;
    }
    wt_all_kernel<<<1536, dim3(32, 8)>>>(wa);

    for (int blk = 0; blk < 2; blk++) {
        int base = 1 + 13 * blk;
        const float* n1g  = (const float*)d_in[base + 0];
        const float* n1b  = (const float*)d_in[base + 1];
        const float* qkvb = (const float*)d_in[base + 3];
        const float* rpb  = (const float*)d_in[base + 4];
        const float* pb   = (const float*)d_in[base + 6];
        const float* n2g  = (const float*)d_in[base + 7];
        const float* n2b  = (const float*)d_in[base + 8];
        const float* f1b  = (const float*)d_in[base + 10];
        const float* f2b  = (const float*)d_in[base + 12];

        __half* wb   = wt + blk * 786432;
        __half* qkvt = wb;
        __half* pwt  = wb + 196608;
        __half* f1t  = wb + 262144;
        __half* f2t  = wb + 524288;

        int shift  = blk ? 4 : 0;
        int masked = blk;
        const float* x_cur = blk ? x : x_in;

        ln_kernel<<<8192, 256>>>(x_cur, n1g, n1b, xw, shift);
        // QKV: N=768 -> grid (3, 512)
        h_gemm_kernel<<<dim3(3, 512), 256, GEMM_SMEM_B>>>(
            xw, qkvt, qkvb, nullptr, qkv, 768, 256, 0, 1);
        attn_tc_kernel<<<4096, 256>>>(qkv, rpb, attnb, masked);
        // proj: N=256 -> grid (1, 512)
        h_gemm_kernel<<<dim3(1, 512), 256, GEMM_SMEM_B>>>(
            attnb, pwt, pb, nullptr, proj, 256, 256, 0, 1);
        rev_ln_kernel<<<8192, 256>>>(proj, x_cur, x, n2g, n2b, h2, shift);
        // MLP1: N=1024 -> grid (4, 512)
        h_gemm_kernel<<<dim3(4, 512), 256, GEMM_SMEM_B>>>(
            h2, f1t, f1b, nullptr, mlp, 1024, 256, 1, 1);
        // MLP2: N=256 -> grid (1, 512)
        h_gemm_kernel<<<dim3(1, 512), 256, GEMM_SMEM_B>>>(
            mlp, f2t, f2b, x, x, 256, 1024, 0, 0);
    }
}

// round 13
// speedup vs baseline: 1.2667x; 1.2667x over previous
#include <cuda_runtime.h>
#include <cuda_fp16.h>
#include <math.h>

// ---------------------------------------------------------------------------
// Swin: B=16, H=W=64, DIM=256, HEADS=8, HD=32, WS=8, N=64, NW=64, MLP_H=1024
// fp16 datapath, fp32 accumulate, fp32 residual stream.
// ---------------------------------------------------------------------------

#define NTOK 65536

static __device__ __half g_xw  [NTOK * 256];
static __device__ __half g_qkv [NTOK * 768];
static __device__ __half g_attn[NTOK * 256];
static __device__ __half g_h2  [NTOK * 256];
static __device__ __half g_mlp [NTOK * 1024];
static __device__ __half g_proj[NTOK * 256];
static __device__ __half g_wt  [2 * 786432];
static __device__ float  g_rbt [2 * 8 * 225];   // rpb transposed [blk][head][225]

__device__ __forceinline__ unsigned pack_h(float x, float y) {
    __half2 h = __floats2half2_rn(x, y);
    return *(unsigned*)&h;
}

// ---------------------------------------------------------------------------
// Merged weight convert+transpose for BOTH blocks: W[K][N] fp32 -> Wt[N][K] fp16
// ---------------------------------------------------------------------------
struct WtArgs {
    const float* w[8];
    __half*      o[8];
};

__global__ void wt_all_kernel(WtArgs args)
{
    __shared__ float tile[32][33];
    int b = blockIdx.x;
    int blk = b >= 768;
    b -= blk * 768;
    const float* W; __half* Wt; int K, N, nb, sel;
    if (b < 192)      { sel = 0; K = 256;  N = 768;  nb = 24; }
    else if (b < 256) { b -= 192; sel = 1; K = 256;  N = 256;  nb = 8; }
    else if (b < 512) { b -= 256; sel = 2; K = 256;  N = 1024; nb = 32; }
    else              { b -= 512; sel = 3; K = 1024; N = 256;  nb = 8; }
    W  = args.w[blk * 4 + sel];
    Wt = args.o[blk * 4 + sel];
    int n0 = (b % nb) << 5, k0 = (b / nb) << 5;
    int tx = threadIdx.x, ty = threadIdx.y;
    #pragma unroll
    for (int i = 0; i < 4; i++)
        tile[ty + i * 8][tx] = W[(size_t)(k0 + ty + i * 8) * N + n0 + tx];
    __syncthreads();
    #pragma unroll
    for (int i = 0; i < 4; i++)
        Wt[(size_t)(n0 + ty + i * 8) * K + k0 + tx] =
            __float2half_rn(tile[tx][ty + i * 8]);
}

// ---------------------------------------------------------------------------
// rpb gather: rpb[225][8] -> rbt[blk][head][225] (coalesced attn reads)
// ---------------------------------------------------------------------------
__global__ void rpb_gather_kernel(const float* __restrict__ rpb0,
                                  const float* __restrict__ rpb1,
                                  float* __restrict__ rbt)
{
    int blk  = blockIdx.x >> 3;
    int head = blockIdx.x & 7;
    const float* rpb = blk ? rpb1 : rpb0;
    int tid = threadIdx.x;
    if (tid < 225)
        rbt[(blk * 8 + head) * 225 + tid] = rpb[tid * 8 + head];
}

// ---------------------------------------------------------------------------
// LayerNorm (+shift + window partition), fp32 in -> fp16 out. One warp/row.
// ---------------------------------------------------------------------------
__global__ void ln_kernel(const float* __restrict__ x,
                          const float* __restrict__ gamma,
                          const float* __restrict__ beta,
                          __half* __restrict__ out,
                          int shift)
{
    int gw   = (blockIdx.x * blockDim.x + threadIdx.x) >> 5;
    int lane = threadIdx.x & 31;
    if (gw >= NTOK) return;

    int win = gw >> 6, n = gw & 63;
    int b  = win >> 6, wi = win & 63;
    int h  = (((wi >> 3) << 3) + (n >> 3) + shift) & 63;
    int w  = (((wi & 7)  << 3) + (n & 7)  + shift) & 63;
    int src = (b << 12) + (h << 6) + w;

    const float4* xr = (const float4*)x + (size_t)src * 64;
    float4 v0 = xr[lane];
    float4 v1 = xr[lane + 32];

    float s = v0.x + v0.y + v0.z + v0.w + v1.x + v1.y + v1.z + v1.w;
    #pragma unroll
    for (int o = 16; o; o >>= 1) s += __shfl_xor_sync(0xffffffffu, s, o);
    float mean = s * (1.0f / 256.0f);

    float a, ss = 0.f;
    a = v0.x - mean; ss += a * a;  a = v0.y - mean; ss += a * a;
    a = v0.z - mean; ss += a * a;  a = v0.w - mean; ss += a * a;
    a = v1.x - mean; ss += a * a;  a = v1.y - mean; ss += a * a;
    a = v1.z - mean; ss += a * a;  a = v1.w - mean; ss += a * a;
    #pragma unroll
    for (int o = 16; o; o >>= 1) ss += __shfl_xor_sync(0xffffffffu, ss, o);
    float rstd = rsqrtf(ss * (1.0f / 256.0f) + 1e-5f);

    const float4* g4 = (const float4*)gamma;
    const float4* b4 = (const float4*)beta;
    float4 g0 = g4[lane], g1 = g4[lane + 32];
    float4 c0 = b4[lane], c1 = b4[lane + 32];

    unsigned* o32 = (unsigned*)(out + (size_t)gw * 256);
    uint2 r0, r1;
    r0.x = pack_h((v0.x - mean) * rstd * g0.x + c0.x,
                  (v0.y - mean) * rstd * g0.y + c0.y);
    r0.y = pack_h((v0.z - mean) * rstd * g0.z + c0.z,
                  (v0.w - mean) * rstd * g0.w + c0.w);
    r1.x = pack_h((v1.x - mean) * rstd * g1.x + c1.x,
                  (v1.y - mean) * rstd * g1.y + c1.y);
    r1.y = pack_h((v1.z - mean) * rstd * g1.z + c1.z,
                  (v1.w - mean) * rstd * g1.w + c1.w);
    *(uint2*)(o32 + lane * 2)      = r0;
    *(uint2*)(o32 + 64 + lane * 2) = r1;
}

// ---------------------------------------------------------------------------
// Fused window-reverse + un-shift + residual + LayerNorm2.
// ---------------------------------------------------------------------------
__global__ void rev_ln_kernel(const __half* __restrict__ proj,
                              const float* __restrict__ x_src,
                              float* __restrict__ x_dst,
                              const float* __restrict__ gamma,
                              const float* __restrict__ beta,
                              __half* __restrict__ h2,
                              int shift)
{
    int gw   = (blockIdx.x * blockDim.x + threadIdx.x) >> 5;
    int lane = threadIdx.x & 31;
    if (gw >= NTOK) return;

    int b = gw >> 12, h = (gw >> 6) & 63, w = gw & 63;
    int hh = (h - shift) & 63, ww = (w - shift) & 63;
    int row = ((b << 6) + ((hh >> 3) << 3) + (ww >> 3)) * 64
            + ((hh & 7) << 3) + (ww & 7);

    const __half2* pr = (const __half2*)(proj + (size_t)row * 256);
    const float4* xr = (const float4*)x_src + (size_t)gw * 64;
    float4 v0 = xr[lane],      v1 = xr[lane + 32];
    __half2 pa = pr[lane * 2],      pb = pr[lane * 2 + 1];
    __half2 pc = pr[64 + lane * 2], pd = pr[64 + lane * 2 + 1];
    float2 fa = __half22float2(pa), fb = __half22float2(pb);
    float2 fc = __half22float2(pc), fd = __half22float2(pd);
    v0.x += fa.x; v0.y += fa.y; v0.z += fb.x; v0.w += fb.y;
    v1.x += fc.x; v1.y += fc.y; v1.z += fd.x; v1.w += fd.y;

    float4* xo = (float4*)x_dst + (size_t)gw * 64;
    xo[lane]      = v0;
    xo[lane + 32] = v1;

    float s = v0.x + v0.y + v0.z + v0.w + v1.x + v1.y + v1.z + v1.w;
    #pragma unroll
    for (int o = 16; o; o >>= 1) s += __shfl_xor_sync(0xffffffffu, s, o);
    float mean = s * (1.0f / 256.0f);

    float a, ss = 0.f;
    a = v0.x - mean; ss += a * a;  a = v0.y - mean; ss += a * a;
    a = v0.z - mean; ss += a * a;  a = v0.w - mean; ss += a * a;
    a = v1.x - mean; ss += a * a;  a = v1.y - mean; ss += a * a;
    a = v1.z - mean; ss += a * a;  a = v1.w - mean; ss += a * a;
    #pragma unroll
    for (int o = 16; o; o >>= 1) ss += __shfl_xor_sync(0xffffffffu, ss, o);
    float rstd = rsqrtf(ss * (1.0f / 256.0f) + 1e-5f);

    const float4* g4 = (const float4*)gamma;
    const float4* b4 = (const float4*)beta;
    float4 g0 = g4[lane], g1 = g4[lane + 32];
    float4 c0 = b4[lane], c1 = b4[lane + 32];

    unsigned* o32 = (unsigned*)(h2 + (size_t)gw * 256);
    uint2 r0, r1;
    r0.x = pack_h((v0.x - mean) * rstd * g0.x + c0.x,
                  (v0.y - mean) * rstd * g0.y + c0.y);
    r0.y = pack_h((v0.z - mean) * rstd * g0.z + c0.z,
                  (v0.w - mean) * rstd * g0.w + c0.w);
    r1.x = pack_h((v1.x - mean) * rstd * g1.x + c1.x,
                  (v1.y - mean) * rstd * g1.y + c1.y);
    r1.y = pack_h((v1.z - mean) * rstd * g1.z + c1.z,
                  (v1.w - mean) * rstd * g1.w + c1.w);
    *(uint2*)(o32 + lane * 2)      = r0;
    *(uint2*)(o32 + 64 + lane * 2) = r1;
}

// ---------------------------------------------------------------------------
// fp16 tensor-core GEMM (R10, known 1071us config): 128x128x32, 8 warps,
// m16n8k16, 4-stage cp.async, single __syncthreads/iter, ldmatrix.x4.
// ---------------------------------------------------------------------------
#define HSTRIDE 40
#define STG (128 * HSTRIDE)

__device__ __forceinline__ void cp16(void* s, const void* g) {
    unsigned sa = (unsigned)__cvta_generic_to_shared(s);
    asm volatile("cp.async.cg.shared.global [%0], [%1], 16;" :: "r"(sa), "l"(g));
}

__device__ __forceinline__ void ldm4(unsigned& r0, unsigned& r1,
                                     unsigned& r2, unsigned& r3, unsigned addr) {
    asm volatile("ldmatrix.sync.aligned.m8n8.x4.shared.b16 {%0,%1,%2,%3}, [%4];"
                 : "=r"(r0), "=r"(r1), "=r"(r2), "=r"(r3) : "r"(addr));
}

__device__ __forceinline__ void ldm2t(unsigned& r0, unsigned& r1, unsigned addr) {
    asm volatile("ldmatrix.sync.aligned.m8n8.x2.trans.shared.b16 {%0,%1}, [%2];"
                 : "=r"(r0), "=r"(r1) : "r"(addr));
}

__global__ void __launch_bounds__(256, 2)
h_gemm_kernel(const __half* __restrict__ A,
              const __half* __restrict__ Bt,
              const float* __restrict__ bias,
              const float* __restrict__ R,
              void* __restrict__ Cv,
              int N, int K, int act, int out_h16)
{
    extern __shared__ __half smem[];
    __half* As = smem;                 // 4 stages
    __half* Bs = smem + 4 * STG;

    int tid  = threadIdx.x;
    int bm   = blockIdx.y << 7;
    int bn   = blockIdx.x << 7;
    int wid  = tid >> 5, lane = tid & 31;
    int wm   = (wid & 3) << 5;
    int wn   = (wid >> 2) << 6;
    int g    = lane >> 2, t = lane & 3;

    float acc[2][8][4];
    #pragma unroll
    for (int mi = 0; mi < 2; mi++)
        #pragma unroll
        for (int ni = 0; ni < 8; ni++)
            #pragma unroll
            for (int c = 0; c < 4; c++) acc[mi][ni][c] = 0.f;

    int a_m = tid >> 2;
    int a_k = (tid & 3) << 3;
    int iters = K >> 5;

    unsigned as_u = (unsigned)__cvta_generic_to_shared(As);
    unsigned bs_u = (unsigned)__cvta_generic_to_shared(Bs);
    int a_off = (wm + (lane & 15)) * HSTRIDE + ((lane >> 4) << 3);
    int b_off = (wn + ((lane >> 4) << 3) + (lane & 7)) * HSTRIDE
              + (((lane >> 3) & 1) << 3);

    #define LOAD_STAGE(si, kb)                                                  \
    {                                                                           \
        __half* as = As + (si) * STG;                                           \
        __half* bs = Bs + (si) * STG;                                           \
        cp16(as + a_m * HSTRIDE + a_k,                                          \
             A + (size_t)(bm + a_m) * K + (kb) + a_k);                          \
        cp16(as + (a_m + 64) * HSTRIDE + a_k,                                   \
             A + (size_t)(bm + a_m + 64) * K + (kb) + a_k);                     \
        cp16(bs + a_m * HSTRIDE + a_k,                                          \
             Bt + (size_t)(bn + a_m) * K + (kb) + a_k);                         \
        cp16(bs + (a_m + 64) * HSTRIDE + a_k,                                   \
             Bt + (size_t)(bn + a_m + 64) * K + (kb) + a_k);                    \
        asm volatile("cp.async.commit_group;");                                 \
    }

    LOAD_STAGE(0, 0)
    LOAD_STAGE(1, 32)
    LOAD_STAGE(2, 64)

    for (int i = 0; i < iters; i++) {
        if (i + 3 <= iters) {
            asm volatile("cp.async.wait_group 2;");
        } else if (i + 2 == iters) {
            asm volatile("cp.async.wait_group 1;");
        } else {
            asm volatile("cp.async.wait_group 0;");
        }
        __syncthreads();

        if (i + 3 < iters) LOAD_STAGE((i + 3) & 3, (i + 3) << 5)

        unsigned abase = as_u + ((i & 3) * STG) * 2;
        unsigned bbase = bs_u + ((i & 3) * STG) * 2;
        #pragma unroll
        for (int kk = 0; kk < 2; kk++) {
            int k0 = kk << 4;
            unsigned af[2][4], bf[8][2];
            #pragma unroll
            for (int mi = 0; mi < 2; mi++)
                ldm4(af[mi][0], af[mi][1], af[mi][2], af[mi][3],
                     abase + (a_off + (mi << 4) * HSTRIDE + k0) * 2);
            #pragma unroll
            for (int p = 0; p < 4; p++)
                ldm4(bf[2 * p][0], bf[2 * p][1], bf[2 * p + 1][0], bf[2 * p + 1][1],
                     bbase + (b_off + (p << 4) * HSTRIDE + k0) * 2);
            #pragma unroll
            for (int mi = 0; mi < 2; mi++)
                #pragma unroll
                for (int ni = 0; ni < 8; ni++) {
                    asm("mma.sync.aligned.m16n8k16.row.col.f32.f16.f16.f32 "
                        "{%0,%1,%2,%3}, {%4,%5,%6,%7}, {%8,%9}, {%0,%1,%2,%3};"
                        : "+f"(acc[mi][ni][0]), "+f"(acc[mi][ni][1]),
                          "+f"(acc[mi][ni][2]), "+f"(acc[mi][ni][3])
                        : "r"(af[mi][0]), "r"(af[mi][1]), "r"(af[mi][2]), "r"(af[mi][3]),
                          "r"(bf[ni][0]), "r"(bf[ni][1]));
                }
        }
    }

    #pragma unroll
    for (int mi = 0; mi < 2; mi++) {
        int row0 = bm + wm + (mi << 4) + g;
        #pragma unroll
        for (int ni = 0; ni < 8; ni++) {
            int col = bn + wn + (ni << 3) + (t << 1);
            float2 bb = *(const float2*)(bias + col);
            float2 u, v;
            u.x = acc[mi][ni][0] + bb.x;
            u.y = acc[mi][ni][1] + bb.y;
            v.x = acc[mi][ni][2] + bb.x;
            v.y = acc[mi][ni][3] + bb.y;
            if (act) {
                u.x = 0.5f * u.x * (1.f + erff(u.x * 0.70710678118654752f));
                u.y = 0.5f * u.y * (1.f + erff(u.y * 0.70710678118654752f));
                v.x = 0.5f * v.x * (1.f + erff(v.x * 0.70710678118654752f));
                v.y = 0.5f * v.y * (1.f + erff(v.y * 0.70710678118654752f));
            }
            size_t o0 = (size_t)row0 * N + col;
            size_t o1 = (size_t)(row0 + 8) * N + col;
            if (out_h16) {
                unsigned* C = (unsigned*)Cv;
                C[o0 >> 1] = pack_h(u.x, u.y);
                C[o1 >> 1] = pack_h(v.x, v.y);
            } else {
                float* C = (float*)Cv;
                if (R) {
                    float2 r0 = *(const float2*)(R + o0);
                    float2 r1 = *(const float2*)(R + o1);
                    u.x += r0.x; u.y += r0.y; v.x += r1.x; v.y += r1.y;
                }
                *(float2*)(C + o0) = u;
                *(float2*)(C + o1) = v;
            }
        }
    }
}

// ---------------------------------------------------------------------------
// fp16 tensor-core window attention: 2 windows (same head) per 256-thread CTA.
// Q staged through ps (reused for P); all fragments via ldmatrix; rb coalesced.
// ---------------------------------------------------------------------------
__global__ void __launch_bounds__(256)
attn_tc_kernel(const __half* __restrict__ qkv,
               const float* __restrict__ rbt,   // [head][225], this block's slice
               __half* __restrict__ out,
               int masked)
{
    __shared__ __half ks[2][64][40];
    __shared__ __half vs[2][64][40];
    __shared__ __half ps[2][64][72];
    __shared__ float rb[232];

    const float SCALE = 0.17677669529663687f;

    int idx  = blockIdx.x;
    int head = idx & 7;
    int wp   = idx >> 3;
    int tid  = threadIdx.x;
    int warp = tid >> 5, lane = tid & 31;
    int g = lane >> 2, t = lane & 3;

    {
        int sw   = tid >> 7;
        int stid = tid & 127;
        int tok  = stid >> 1;
        int half = (stid & 1) << 4;
        const __half* bq = qkv + (size_t)((wp * 2 + sw) * 64 + tok) * 768 + head * 32 + half;
        uint4 qa = *(const uint4*)(bq);
        uint4 qb = *(const uint4*)(bq + 8);
        *(uint4*)&ps[sw][tok][half]     = qa;
        *(uint4*)&ps[sw][tok][half + 8] = qb;
        uint4 ka = *(const uint4*)(bq + 256);
        uint4 kb = *(const uint4*)(bq + 264);
        *(uint4*)&ks[sw][tok][half]     = ka;
        *(uint4*)&ks[sw][tok][half + 8] = kb;
        uint4 va = *(const uint4*)(bq + 512);
        uint4 vb = *(const uint4*)(bq + 520);
        *(uint4*)&vs[sw][tok][half]     = va;
        *(uint4*)&vs[sw][tok][half + 8] = vb;
    }
    if (tid < 225) rb[tid] = rbt[head * 225 + tid];   // coalesced
    __syncthreads();

    int wloc = warp >> 2;
    int win  = wp * 2 + wloc;
    int wm   = (warp & 3) << 4;
    int i_lo = wm + g, i_hi = i_lo + 8;

    unsigned ks_u = (unsigned)__cvta_generic_to_shared(&ks[wloc][0][0]);
    unsigned vs_u = (unsigned)__cvta_generic_to_shared(&vs[wloc][0][0]);
    unsigned ps_u = (unsigned)__cvta_generic_to_shared(&ps[wloc][0][0]);
    int b_off = (((lane >> 4) << 3) + (lane & 7)) * 40 + (((lane >> 3) & 1) << 3);
    int a_off = (wm + (lane & 15)) * 72 + ((lane >> 4) << 3);

    float sacc[8][4];
    #pragma unroll
    for (int ni = 0; ni < 8; ni++)
        #pragma unroll
        for (int c = 0; c < 4; c++) sacc[ni][c] = 0.f;

    #pragma unroll
    for (int kk = 0; kk < 2; kk++) {
        int k0 = kk << 4;
        unsigned qf[4];
        ldm4(qf[0], qf[1], qf[2], qf[3], ps_u + (a_off + k0) * 2);
        unsigned bf[8][2];
        #pragma unroll
        for (int p = 0; p < 4; p++)
            ldm4(bf[2 * p][0], bf[2 * p][1], bf[2 * p + 1][0], bf[2 * p + 1][1],
                 ks_u + (b_off + (p << 4) * 40 + k0) * 2);
        #pragma unroll
        for (int ni = 0; ni < 8; ni++) {
            asm("mma.sync.aligned.m16n8k16.row.col.f32.f16.f16.f32 "
                "{%0,%1,%2,%3}, {%4,%5,%6,%7}, {%8,%9}, {%0,%1,%2,%3};"
                : "+f"(sacc[ni][0]), "+f"(sacc[ni][1]),
                  "+f"(sacc[ni][2]), "+f"(sacc[ni][3])
                : "r"(qf[0]), "r"(qf[1]), "r"(qf[2]), "r"(qf[3]),
                  "r"(bf[ni][0]), "r"(bf[ni][1]));
        }
    }

    int yi0 = i_lo >> 3, xi0 = i_lo & 7;
    int yi1 = i_hi >> 3, xi1 = i_hi & 7;
    int wi = win & 63;
    int whbase = (wi >> 3) << 3;
    int wwbase = (wi & 7) << 3;
    int reg0 = 0, reg1 = 0;
    if (masked) {
        int h0 = whbase + yi0, w0 = wwbase + xi0;
        int h1 = whbase + yi1, w1 = wwbase + xi1;
        reg0 = ((h0 >= 56) + (h0 >= 60)) * 3 + (w0 >= 56) + (w0 >= 60);
        reg1 = ((h1 >= 56) + (h1 >= 60)) * 3 + (w1 >= 56) + (w1 >= 60);
    }
    #pragma unroll
    for (int ni = 0; ni < 8; ni++) {
        #pragma unroll
        for (int c = 0; c < 2; c++) {
            int j = (ni << 3) + (t << 1) + c;
            int yj = j >> 3, xj = j & 7;
            sacc[ni][c]     = sacc[ni][c]     * SCALE + rb[(yi0 - yj + 7) * 15 + (xi0 - xj + 7)];
            sacc[ni][2 + c] = sacc[ni][2 + c] * SCALE + rb[(yi1 - yj + 7) * 15 + (xi1 - xj + 7)];
            if (masked) {
                int hj = whbase + yj, wj = wwbase + xj;
                int regj = ((hj >= 56) + (hj >= 60)) * 3 + (wj >= 56) + (wj >= 60);
                if (regj != reg0) sacc[ni][c]     -= 100.f;
                if (regj != reg1) sacc[ni][2 + c] -= 100.f;
            }
        }
    }

    float mlo = -1e30f, mhi = -1e30f;
    #pragma unroll
    for (int ni = 0; ni < 8; ni++) {
        mlo = fmaxf(mlo, fmaxf(sacc[ni][0], sacc[ni][1]));
        mhi = fmaxf(mhi, fmaxf(sacc[ni][2], sacc[ni][3]));
    }
    mlo = fmaxf(mlo, __shfl_xor_sync(0xffffffffu, mlo, 1));
    mlo = fmaxf(mlo, __shfl_xor_sync(0xffffffffu, mlo, 2));
    mhi = fmaxf(mhi, __shfl_xor_sync(0xffffffffu, mhi, 1));
    mhi = fmaxf(mhi, __shfl_xor_sync(0xffffffffu, mhi, 2));

    float slo = 0.f, shi = 0.f;
    #pragma unroll
    for (int ni = 0; ni < 8; ni++) {
        sacc[ni][0] = __expf(sacc[ni][0] - mlo);
        sacc[ni][1] = __expf(sacc[ni][1] - mlo);
        sacc[ni][2] = __expf(sacc[ni][2] - mhi);
        sacc[ni][3] = __expf(sacc[ni][3] - mhi);
        slo += sacc[ni][0] + sacc[ni][1];
        shi += sacc[ni][2] + sacc[ni][3];
    }
    slo += __shfl_xor_sync(0xffffffffu, slo, 1);
    slo += __shfl_xor_sync(0xffffffffu, slo, 2);
    shi += __shfl_xor_sync(0xffffffffu, shi, 1);
    shi += __shfl_xor_sync(0xffffffffu, shi, 2);
    float inv_lo = 1.f / slo, inv_hi = 1.f / shi;

    #pragma unroll
    for (int ni = 0; ni < 8; ni++) {
        *(unsigned*)&ps[wloc][i_lo][(ni << 3) + (t << 1)] = pack_h(sacc[ni][0], sacc[ni][1]);
        *(unsigned*)&ps[wloc][i_hi][(ni << 3) + (t << 1)] = pack_h(sacc[ni][2], sacc[ni][3]);
    }
    __syncwarp();

    float oacc[4][4];
    #pragma unroll
    for (int ni = 0; ni < 4; ni++)
        #pragma unroll
        for (int c = 0; c < 4; c++) oacc[ni][c] = 0.f;

    #pragma unroll
    for (int kk = 0; kk < 4; kk++) {
        int k0 = kk << 4;
        unsigned af[4];
        ldm4(af[0], af[1], af[2], af[3], ps_u + (a_off + k0) * 2);
        #pragma unroll
        for (int ni = 0; ni < 4; ni++) {
            unsigned b0, b1;
            ldm2t(b0, b1, vs_u + ((k0 + (lane & 15)) * 40 + (ni << 3)) * 2);
            asm("mma.sync.aligned.m16n8k16.row.col.f32.f16.f16.f32 "
                "{%0,%1,%2,%3}, {%4,%5,%6,%7}, {%8,%9}, {%0,%1,%2,%3};"
                : "+f"(oacc[ni][0]), "+f"(oacc[ni][1]),
                  "+f"(oacc[ni][2]), "+f"(oacc[ni][3])
                : "r"(af[0]), "r"(af[1]), "r"(af[2]), "r"(af[3]),
                  "r"(b0), "r"(b1));
        }
    }

    __half* olo = out + (size_t)(win * 64 + i_lo) * 256 + head * 32;
    __half* ohi = out + (size_t)(win * 64 + i_hi) * 256 + head * 32;
    #pragma unroll
    for (int ni = 0; ni < 4; ni++) {
        int col = (ni << 3) + (t << 1);
        *(unsigned*)(olo + col) = pack_h(oacc[ni][0] * inv_lo, oacc[ni][1] * inv_lo);
        *(unsigned*)(ohi + col) = pack_h(oacc[ni][2] * inv_hi, oacc[ni][3] * inv_hi);
    }
}

// ---------------------------------------------------------------------------
extern "C" void kernel_launch(void* const* d_in, const int* in_sizes, int n_in,
                              void* d_out, int out_size)
{
    (void)in_sizes; (void)n_in; (void)out_size;

    __half *xw, *qkv, *attnb, *h2, *mlp, *wt, *proj;
    float* rbt;
    cudaGetSymbolAddress((void**)&xw,    g_xw);
    cudaGetSymbolAddress((void**)&qkv,   g_qkv);
    cudaGetSymbolAddress((void**)&attnb, g_attn);
    cudaGetSymbolAddress((void**)&h2,    g_h2);
    cudaGetSymbolAddress((void**)&mlp,   g_mlp);
    cudaGetSymbolAddress((void**)&proj,  g_proj);
    cudaGetSymbolAddress((void**)&wt,    g_wt);
    cudaGetSymbolAddress((void**)&rbt,   g_rbt);

    const int GEMM_SMEM = 8 * STG * (int)sizeof(__half);  // 81920 B
    cudaFuncSetAttribute(h_gemm_kernel,
                         cudaFuncAttributeMaxDynamicSharedMemorySize, GEMM_SMEM);

    const float* x_in = (const float*)d_in[0];
    float* x = (float*)d_out;

    WtArgs wa;
    for (int blk = 0; blk < 2; blk++) {
        int base = 1 + 13 * blk;
        wa.w[blk * 4 + 0] = (const float*)d_in[base + 2];
        wa.w[blk * 4 + 1] = (const float*)d_in[base + 5];
        wa.w[blk * 4 + 2] = (const float*)d_in[base + 9];
        wa.w[blk * 4 + 3] = (const float*)d_in[base + 11];
        __half* wb = wt + blk * 786432;
        wa.o[blk * 4 + 0] = wb;
        wa.o[blk * 4 + 1] = wb + 196608;
        wa.o[blk * 4 + 2] = wb + 262144;
        wa.o[blk * 4 + 3] = wb + 524288;
    }
    wt_all_kernel<<<1536, dim3(32, 8)>>>(wa);
    rpb_gather_kernel<<<16, 256>>>((const float*)d_in[1 + 4],
                                   (const float*)d_in[1 + 13 + 4], rbt);

    for (int blk = 0; blk < 2; blk++) {
        int base = 1 + 13 * blk;
        const float* n1g  = (const float*)d_in[base + 0];
        const float* n1b  = (const float*)d_in[base + 1];
        const float* qkvb = (const float*)d_in[base + 3];
        const float* pb   = (const float*)d_in[base + 6];
        const float* n2g  = (const float*)d_in[base + 7];
        const float* n2b  = (const float*)d_in[base + 8];
        const float* f1b  = (const float*)d_in[base + 10];
        const float* f2b  = (const float*)d_in[base + 12];

        __half* wb   = wt + blk * 786432;
        __half* qkvt = wb;
        __half* pwt  = wb + 196608;
        __half* f1t  = wb + 262144;
        __half* f2t  = wb + 524288;

        int shift  = blk ? 4 : 0;
        int masked = blk;
        const float* x_cur = blk ? x : x_in;

        ln_kernel<<<8192, 256>>>(x_cur, n1g, n1b, xw, shift);
        h_gemm_kernel<<<dim3(6, 512), 256, GEMM_SMEM>>>(
            xw, qkvt, qkvb, nullptr, qkv, 768, 256, 0, 1);
        attn_tc_kernel<<<4096, 256>>>(qkv, rbt + blk * 8 * 225, attnb, masked);
        h_gemm_kernel<<<dim3(2, 512), 256, GEMM_SMEM>>>(
            attnb, pwt, pb, nullptr, proj, 256, 256, 0, 1);
        rev_ln_kernel<<<8192, 256>>>(proj, x_cur, x, n2g, n2b, h2, shift);
        h_gemm_kernel<<<dim3(8, 512), 256, GEMM_SMEM>>>(
            h2, f1t, f1b, nullptr, mlp, 1024, 256, 1, 1);
        h_gemm_kernel<<<dim3(2, 512), 256, GEMM_SMEM>>>(
            mlp, f2t, f2b, x, x, 256, 1024, 0, 0);
    }
}

// round 14
// speedup vs baseline: 1.3425x; 1.0598x over previous
#include <cuda_runtime.h>
#include <cuda_fp16.h>
#include <math.h>

// ---------------------------------------------------------------------------
// Swin: B=16, H=W=64, DIM=256, HEADS=8, HD=32, WS=8, N=64, NW=64, MLP_H=1024
// fp16 datapath, fp32 accumulate, fp32 residual stream.
// ---------------------------------------------------------------------------

#define NTOK 65536

static __device__ __half g_xw  [NTOK * 256];
static __device__ __half g_qkv [NTOK * 768];
static __device__ __half g_attn[NTOK * 256];
static __device__ __half g_h2  [NTOK * 256];
static __device__ __half g_mlp [NTOK * 1024];
static __device__ __half g_proj[NTOK * 256];
static __device__ __half g_wt  [2 * 786432];
static __device__ float  g_rbt [2 * 8 * 225];

__device__ __forceinline__ unsigned pack_h(float x, float y) {
    __half2 h = __floats2half2_rn(x, y);
    return *(unsigned*)&h;
}

// ---------------------------------------------------------------------------
// Merged weight convert+transpose for BOTH blocks: W[K][N] fp32 -> Wt[N][K] fp16
// ---------------------------------------------------------------------------
struct WtArgs {
    const float* w[8];
    __half*      o[8];
};

__global__ void wt_all_kernel(WtArgs args)
{
    __shared__ float tile[32][33];
    int b = blockIdx.x;
    int blk = b >= 768;
    b -= blk * 768;
    const float* W; __half* Wt; int K, N, nb, sel;
    if (b < 192)      { sel = 0; K = 256;  N = 768;  nb = 24; }
    else if (b < 256) { b -= 192; sel = 1; K = 256;  N = 256;  nb = 8; }
    else if (b < 512) { b -= 256; sel = 2; K = 256;  N = 1024; nb = 32; }
    else              { b -= 512; sel = 3; K = 1024; N = 256;  nb = 8; }
    W  = args.w[blk * 4 + sel];
    Wt = args.o[blk * 4 + sel];
    int n0 = (b % nb) << 5, k0 = (b / nb) << 5;
    int tx = threadIdx.x, ty = threadIdx.y;
    #pragma unroll
    for (int i = 0; i < 4; i++)
        tile[ty + i * 8][tx] = W[(size_t)(k0 + ty + i * 8) * N + n0 + tx];
    __syncthreads();
    #pragma unroll
    for (int i = 0; i < 4; i++)
        Wt[(size_t)(n0 + ty + i * 8) * K + k0 + tx] =
            __float2half_rn(tile[tx][ty + i * 8]);
}

// ---------------------------------------------------------------------------
// rpb gather: rpb[225][8] -> rbt[blk][head][225]
// ---------------------------------------------------------------------------
__global__ void rpb_gather_kernel(const float* __restrict__ rpb0,
                                  const float* __restrict__ rpb1,
                                  float* __restrict__ rbt)
{
    int blk  = blockIdx.x >> 3;
    int head = blockIdx.x & 7;
    const float* rpb = blk ? rpb1 : rpb0;
    int tid = threadIdx.x;
    if (tid < 225)
        rbt[(blk * 8 + head) * 225 + tid] = rpb[tid * 8 + head];
}

// ---------------------------------------------------------------------------
// LayerNorm (+shift + window partition), fp32 in -> fp16 out. One warp/row.
// ---------------------------------------------------------------------------
__global__ void ln_kernel(const float* __restrict__ x,
                          const float* __restrict__ gamma,
                          const float* __restrict__ beta,
                          __half* __restrict__ out,
                          int shift)
{
    int gw   = (blockIdx.x * blockDim.x + threadIdx.x) >> 5;
    int lane = threadIdx.x & 31;
    if (gw >= NTOK) return;

    int win = gw >> 6, n = gw & 63;
    int b  = win >> 6, wi = win & 63;
    int h  = (((wi >> 3) << 3) + (n >> 3) + shift) & 63;
    int w  = (((wi & 7)  << 3) + (n & 7)  + shift) & 63;
    int src = (b << 12) + (h << 6) + w;

    const float4* xr = (const float4*)x + (size_t)src * 64;
    float4 v0 = xr[lane];
    float4 v1 = xr[lane + 32];

    float s = v0.x + v0.y + v0.z + v0.w + v1.x + v1.y + v1.z + v1.w;
    #pragma unroll
    for (int o = 16; o; o >>= 1) s += __shfl_xor_sync(0xffffffffu, s, o);
    float mean = s * (1.0f / 256.0f);

    float a, ss = 0.f;
    a = v0.x - mean; ss += a * a;  a = v0.y - mean; ss += a * a;
    a = v0.z - mean; ss += a * a;  a = v0.w - mean; ss += a * a;
    a = v1.x - mean; ss += a * a;  a = v1.y - mean; ss += a * a;
    a = v1.z - mean; ss += a * a;  a = v1.w - mean; ss += a * a;
    #pragma unroll
    for (int o = 16; o; o >>= 1) ss += __shfl_xor_sync(0xffffffffu, ss, o);
    float rstd = rsqrtf(ss * (1.0f / 256.0f) + 1e-5f);

    const float4* g4 = (const float4*)gamma;
    const float4* b4 = (const float4*)beta;
    float4 g0 = g4[lane], g1 = g4[lane + 32];
    float4 c0 = b4[lane], c1 = b4[lane + 32];

    unsigned* o32 = (unsigned*)(out + (size_t)gw * 256);
    uint2 r0, r1;
    r0.x = pack_h((v0.x - mean) * rstd * g0.x + c0.x,
                  (v0.y - mean) * rstd * g0.y + c0.y);
    r0.y = pack_h((v0.z - mean) * rstd * g0.z + c0.z,
                  (v0.w - mean) * rstd * g0.w + c0.w);
    r1.x = pack_h((v1.x - mean) * rstd * g1.x + c1.x,
                  (v1.y - mean) * rstd * g1.y + c1.y);
    r1.y = pack_h((v1.z - mean) * rstd * g1.z + c1.z,
                  (v1.w - mean) * rstd * g1.w + c1.w);
    *(uint2*)(o32 + lane * 2)      = r0;
    *(uint2*)(o32 + 64 + lane * 2) = r1;
}

// ---------------------------------------------------------------------------
// Fused window-reverse + un-shift + residual + LayerNorm2.
// ---------------------------------------------------------------------------
__global__ void rev_ln_kernel(const __half* __restrict__ proj,
                              const float* __restrict__ x_src,
                              float* __restrict__ x_dst,
                              const float* __restrict__ gamma,
                              const float* __restrict__ beta,
                              __half* __restrict__ h2,
                              int shift)
{
    int gw   = (blockIdx.x * blockDim.x + threadIdx.x) >> 5;
    int lane = threadIdx.x & 31;
    if (gw >= NTOK) return;

    int b = gw >> 12, h = (gw >> 6) & 63, w = gw & 63;
    int hh = (h - shift) & 63, ww = (w - shift) & 63;
    int row = ((b << 6) + ((hh >> 3) << 3) + (ww >> 3)) * 64
            + ((hh & 7) << 3) + (ww & 7);

    const __half2* pr = (const __half2*)(proj + (size_t)row * 256);
    const float4* xr = (const float4*)x_src + (size_t)gw * 64;
    float4 v0 = xr[lane],      v1 = xr[lane + 32];
    __half2 pa = pr[lane * 2],      pb = pr[lane * 2 + 1];
    __half2 pc = pr[64 + lane * 2], pd = pr[64 + lane * 2 + 1];
    float2 fa = __half22float2(pa), fb = __half22float2(pb);
    float2 fc = __half22float2(pc), fd = __half22float2(pd);
    v0.x += fa.x; v0.y += fa.y; v0.z += fb.x; v0.w += fb.y;
    v1.x += fc.x; v1.y += fc.y; v1.z += fd.x; v1.w += fd.y;

    float4* xo = (float4*)x_dst + (size_t)gw * 64;
    xo[lane]      = v0;
    xo[lane + 32] = v1;

    float s = v0.x + v0.y + v0.z + v0.w + v1.x + v1.y + v1.z + v1.w;
    #pragma unroll
    for (int o = 16; o; o >>= 1) s += __shfl_xor_sync(0xffffffffu, s, o);
    float mean = s * (1.0f / 256.0f);

    float a, ss = 0.f;
    a = v0.x - mean; ss += a * a;  a = v0.y - mean; ss += a * a;
    a = v0.z - mean; ss += a * a;  a = v0.w - mean; ss += a * a;
    a = v1.x - mean; ss += a * a;  a = v1.y - mean; ss += a * a;
    a = v1.z - mean; ss += a * a;  a = v1.w - mean; ss += a * a;
    #pragma unroll
    for (int o = 16; o; o >>= 1) ss += __shfl_xor_sync(0xffffffffu, ss, o);
    float rstd = rsqrtf(ss * (1.0f / 256.0f) + 1e-5f);

    const float4* g4 = (const float4*)gamma;
    const float4* b4 = (const float4*)beta;
    float4 g0 = g4[lane], g1 = g4[lane + 32];
    float4 c0 = b4[lane], c1 = b4[lane + 32];

    unsigned* o32 = (unsigned*)(h2 + (size_t)gw * 256);
    uint2 r0, r1;
    r0.x = pack_h((v0.x - mean) * rstd * g0.x + c0.x,
                  (v0.y - mean) * rstd * g0.y + c0.y);
    r0.y = pack_h((v0.z - mean) * rstd * g0.z + c0.z,
                  (v0.w - mean) * rstd * g0.w + c0.w);
    r1.x = pack_h((v1.x - mean) * rstd * g1.x + c1.x,
                  (v1.y - mean) * rstd * g1.y + c1.y);
    r1.y = pack_h((v1.z - mean) * rstd * g1.z + c1.z,
                  (v1.w - mean) * rstd * g1.w + c1.w);
    *(uint2*)(o32 + lane * 2)      = r0;
    *(uint2*)(o32 + 64 + lane * 2) = r1;
}

// ---------------------------------------------------------------------------
// fp16 tensor-core GEMM, BK=64: 128x128x64 k-chunks, 8 warps, m16n8k16,
// 3-stage cp.async ring (110.6KB smem, 2 CTAs/SM), half the barriers of BK=32.
// Stride 72 halves (144B) -> ldmatrix phase banks 4r mod 32, conflict-free.
// ---------------------------------------------------------------------------
#define HS64 72
#define STG64 (128 * HS64)                 // halves per matrix per stage
#define GEMM_SMEM64 (3 * 2 * STG64 * 2)    // 110592 bytes

__device__ __forceinline__ void cp16(void* s, const void* g) {
    unsigned sa = (unsigned)__cvta_generic_to_shared(s);
    asm volatile("cp.async.cg.shared.global [%0], [%1], 16;" :: "r"(sa), "l"(g));
}

__device__ __forceinline__ void ldm4(unsigned& r0, unsigned& r1,
                                     unsigned& r2, unsigned& r3, unsigned addr) {
    asm volatile("ldmatrix.sync.aligned.m8n8.x4.shared.b16 {%0,%1,%2,%3}, [%4];"
                 : "=r"(r0), "=r"(r1), "=r"(r2), "=r"(r3) : "r"(addr));
}

__device__ __forceinline__ void ldm2t(unsigned& r0, unsigned& r1, unsigned addr) {
    asm volatile("ldmatrix.sync.aligned.m8n8.x2.trans.shared.b16 {%0,%1}, [%2];"
                 : "=r"(r0), "=r"(r1) : "r"(addr));
}

__global__ void __launch_bounds__(256, 2)
h_gemm_kernel(const __half* __restrict__ A,
              const __half* __restrict__ Bt,
              const float* __restrict__ bias,
              const float* __restrict__ R,
              void* __restrict__ Cv,
              int N, int K, int act, int out_h16)
{
    extern __shared__ __half smem[];
    __half* As = smem;                     // 3 stages A, then 3 stages B
    __half* Bs = smem + 3 * STG64;

    int tid  = threadIdx.x;
    int bm   = blockIdx.y << 7;
    int bn   = blockIdx.x << 7;
    int wid  = tid >> 5, lane = tid & 31;
    int wm   = (wid & 3) << 5;
    int wn   = (wid >> 2) << 6;
    int g    = lane >> 2, t = lane & 3;

    float acc[2][8][4];
    #pragma unroll
    for (int mi = 0; mi < 2; mi++)
        #pragma unroll
        for (int ni = 0; ni < 8; ni++)
            #pragma unroll
            for (int c = 0; c < 4; c++) acc[mi][ni][c] = 0.f;

    int a_m = tid >> 3;               // 0..31 (+32*u)
    int a_k = (tid & 7) << 3;         // 0..56 halves
    int iters = K >> 6;               // 64-wide chunks

    unsigned as_u = (unsigned)__cvta_generic_to_shared(As);
    unsigned bs_u = (unsigned)__cvta_generic_to_shared(Bs);
    int a_off = (wm + (lane & 15)) * HS64 + ((lane >> 4) << 3);
    int b_off = (wn + ((lane >> 4) << 3) + (lane & 7)) * HS64
              + (((lane >> 3) & 1) << 3);

    #define LOAD_STAGE64(si, kb)                                                \
    {                                                                           \
        __half* as = As + (si) * STG64;                                         \
        __half* bs = Bs + (si) * STG64;                                         \
        _Pragma("unroll")                                                       \
        for (int u = 0; u < 4; u++) {                                           \
            int row = a_m + (u << 5);                                           \
            cp16(as + row * HS64 + a_k,                                         \
                 A + (size_t)(bm + row) * K + (kb) + a_k);                      \
            cp16(bs + row * HS64 + a_k,                                         \
                 Bt + (size_t)(bn + row) * K + (kb) + a_k);                     \
        }                                                                       \
        asm volatile("cp.async.commit_group;");                                 \
    }

    LOAD_STAGE64(0, 0)
    LOAD_STAGE64(1, 64)

    for (int i = 0; i < iters; i++) {
        if (i + 1 < iters) asm volatile("cp.async.wait_group 1;");
        else               asm volatile("cp.async.wait_group 0;");
        __syncthreads();   // all warps done with stage (i-1) -> slot (i+2)%3 free

        if (i + 2 < iters) LOAD_STAGE64((i + 2) % 3, (i + 2) << 6)

        unsigned abase = as_u + ((i % 3) * STG64) * 2;
        unsigned bbase = bs_u + ((i % 3) * STG64) * 2;
        #pragma unroll
        for (int kk = 0; kk < 4; kk++) {
            int k0 = kk << 4;
            unsigned af[2][4], bf[8][2];
            #pragma unroll
            for (int mi = 0; mi < 2; mi++)
                ldm4(af[mi][0], af[mi][1], af[mi][2], af[mi][3],
                     abase + (a_off + (mi << 4) * HS64 + k0) * 2);
            #pragma unroll
            for (int p = 0; p < 4; p++)
                ldm4(bf[2 * p][0], bf[2 * p][1], bf[2 * p + 1][0], bf[2 * p + 1][1],
                     bbase + (b_off + (p << 4) * HS64 + k0) * 2);
            #pragma unroll
            for (int mi = 0; mi < 2; mi++)
                #pragma unroll
                for (int ni = 0; ni < 8; ni++) {
                    asm("mma.sync.aligned.m16n8k16.row.col.f32.f16.f16.f32 "
                        "{%0,%1,%2,%3}, {%4,%5,%6,%7}, {%8,%9}, {%0,%1,%2,%3};"
                        : "+f"(acc[mi][ni][0]), "+f"(acc[mi][ni][1]),
                          "+f"(acc[mi][ni][2]), "+f"(acc[mi][ni][3])
                        : "r"(af[mi][0]), "r"(af[mi][1]), "r"(af[mi][2]), "r"(af[mi][3]),
                          "r"(bf[ni][0]), "r"(bf[ni][1]));
                }
        }
    }

    #pragma unroll
    for (int mi = 0; mi < 2; mi++) {
        int row0 = bm + wm + (mi << 4) + g;
        #pragma unroll
        for (int ni = 0; ni < 8; ni++) {
            int col = bn + wn + (ni << 3) + (t << 1);
            float2 bb = *(const float2*)(bias + col);
            float2 u, v;
            u.x = acc[mi][ni][0] + bb.x;
            u.y = acc[mi][ni][1] + bb.y;
            v.x = acc[mi][ni][2] + bb.x;
            v.y = acc[mi][ni][3] + bb.y;
            if (act) {
                u.x = 0.5f * u.x * (1.f + erff(u.x * 0.70710678118654752f));
                u.y = 0.5f * u.y * (1.f + erff(u.y * 0.70710678118654752f));
                v.x = 0.5f * v.x * (1.f + erff(v.x * 0.70710678118654752f));
                v.y = 0.5f * v.y * (1.f + erff(v.y * 0.70710678118654752f));
            }
            size_t o0 = (size_t)row0 * N + col;
            size_t o1 = (size_t)(row0 + 8) * N + col;
            if (out_h16) {
                unsigned* C = (unsigned*)Cv;
                C[o0 >> 1] = pack_h(u.x, u.y);
                C[o1 >> 1] = pack_h(v.x, v.y);
            } else {
                float* C = (float*)Cv;
                if (R) {
                    float2 r0 = *(const float2*)(R + o0);
                    float2 r1 = *(const float2*)(R + o1);
                    u.x += r0.x; u.y += r0.y; v.x += r1.x; v.y += r1.y;
                }
                *(float2*)(C + o0) = u;
                *(float2*)(C + o1) = v;
            }
        }
    }
}

// ---------------------------------------------------------------------------
// fp16 tensor-core window attention (R13): 2 windows per 256-thread CTA.
// ---------------------------------------------------------------------------
__global__ void __launch_bounds__(256)
attn_tc_kernel(const __half* __restrict__ qkv,
               const float* __restrict__ rbt,
               __half* __restrict__ out,
               int masked)
{
    __shared__ __half ks[2][64][40];
    __shared__ __half vs[2][64][40];
    __shared__ __half ps[2][64][72];
    __shared__ float rb[232];

    const float SCALE = 0.17677669529663687f;

    int idx  = blockIdx.x;
    int head = idx & 7;
    int wp   = idx >> 3;
    int tid  = threadIdx.x;
    int warp = tid >> 5, lane = tid & 31;
    int g = lane >> 2, t = lane & 3;

    {
        int sw   = tid >> 7;
        int stid = tid & 127;
        int tok  = stid >> 1;
        int half = (stid & 1) << 4;
        const __half* bq = qkv + (size_t)((wp * 2 + sw) * 64 + tok) * 768 + head * 32 + half;
        uint4 qa = *(const uint4*)(bq);
        uint4 qb = *(const uint4*)(bq + 8);
        *(uint4*)&ps[sw][tok][half]     = qa;
        *(uint4*)&ps[sw][tok][half + 8] = qb;
        uint4 ka = *(const uint4*)(bq + 256);
        uint4 kb = *(const uint4*)(bq + 264);
        *(uint4*)&ks[sw][tok][half]     = ka;
        *(uint4*)&ks[sw][tok][half + 8] = kb;
        uint4 va = *(const uint4*)(bq + 512);
        uint4 vb = *(const uint4*)(bq + 520);
        *(uint4*)&vs[sw][tok][half]     = va;
        *(uint4*)&vs[sw][tok][half + 8] = vb;
    }
    if (tid < 225) rb[tid] = rbt[head * 225 + tid];
    __syncthreads();

    int wloc = warp >> 2;
    int win  = wp * 2 + wloc;
    int wm   = (warp & 3) << 4;
    int i_lo = wm + g, i_hi = i_lo + 8;

    unsigned ks_u = (unsigned)__cvta_generic_to_shared(&ks[wloc][0][0]);
    unsigned vs_u = (unsigned)__cvta_generic_to_shared(&vs[wloc][0][0]);
    unsigned ps_u = (unsigned)__cvta_generic_to_shared(&ps[wloc][0][0]);
    int b_off = (((lane >> 4) << 3) + (lane & 7)) * 40 + (((lane >> 3) & 1) << 3);
    int a_off = (wm + (lane & 15)) * 72 + ((lane >> 4) << 3);

    float sacc[8][4];
    #pragma unroll
    for (int ni = 0; ni < 8; ni++)
        #pragma unroll
        for (int c = 0; c < 4; c++) sacc[ni][c] = 0.f;

    #pragma unroll
    for (int kk = 0; kk < 2; kk++) {
        int k0 = kk << 4;
        unsigned qf[4];
        ldm4(qf[0], qf[1], qf[2], qf[3], ps_u + (a_off + k0) * 2);
        unsigned bf[8][2];
        #pragma unroll
        for (int p = 0; p < 4; p++)
            ldm4(bf[2 * p][0], bf[2 * p][1], bf[2 * p + 1][0], bf[2 * p + 1][1],
                 ks_u + (b_off + (p << 4) * 40 + k0) * 2);
        #pragma unroll
        for (int ni = 0; ni < 8; ni++) {
            asm("mma.sync.aligned.m16n8k16.row.col.f32.f16.f16.f32 "
                "{%0,%1,%2,%3}, {%4,%5,%6,%7}, {%8,%9}, {%0,%1,%2,%3};"
                : "+f"(sacc[ni][0]), "+f"(sacc[ni][1]),
                  "+f"(sacc[ni][2]), "+f"(sacc[ni][3])
                : "r"(qf[0]), "r"(qf[1]), "r"(qf[2]), "r"(qf[3]),
                  "r"(bf[ni][0]), "r"(bf[ni][1]));
        }
    }

    int yi0 = i_lo >> 3, xi0 = i_lo & 7;
    int yi1 = i_hi >> 3, xi1 = i_hi & 7;
    int wi = win & 63;
    int whbase = (wi >> 3) << 3;
    int wwbase = (wi & 7) << 3;
    int reg0 = 0, reg1 = 0;
    if (masked) {
        int h0 = whbase + yi0, w0 = wwbase + xi0;
        int h1 = whbase + yi1, w1 = wwbase + xi1;
        reg0 = ((h0 >= 56) + (h0 >= 60)) * 3 + (w0 >= 56) + (w0 >= 60);
        reg1 = ((h1 >= 56) + (h1 >= 60)) * 3 + (w1 >= 56) + (w1 >= 60);
    }
    #pragma unroll
    for (int ni = 0; ni < 8; ni++) {
        #pragma unroll
        for (int c = 0; c < 2; c++) {
            int j = (ni << 3) + (t << 1) + c;
            int yj = j >> 3, xj = j & 7;
            sacc[ni][c]     = sacc[ni][c]     * SCALE + rb[(yi0 - yj + 7) * 15 + (xi0 - xj + 7)];
            sacc[ni][2 + c] = sacc[ni][2 + c] * SCALE + rb[(yi1 - yj + 7) * 15 + (xi1 - xj + 7)];
            if (masked) {
                int hj = whbase + yj, wj = wwbase + xj;
                int regj = ((hj >= 56) + (hj >= 60)) * 3 + (wj >= 56) + (wj >= 60);
                if (regj != reg0) sacc[ni][c]     -= 100.f;
                if (regj != reg1) sacc[ni][2 + c] -= 100.f;
            }
        }
    }

    float mlo = -1e30f, mhi = -1e30f;
    #pragma unroll
    for (int ni = 0; ni < 8; ni++) {
        mlo = fmaxf(mlo, fmaxf(sacc[ni][0], sacc[ni][1]));
        mhi = fmaxf(mhi, fmaxf(sacc[ni][2], sacc[ni][3]));
    }
    mlo = fmaxf(mlo, __shfl_xor_sync(0xffffffffu, mlo, 1));
    mlo = fmaxf(mlo, __shfl_xor_sync(0xffffffffu, mlo, 2));
    mhi = fmaxf(mhi, __shfl_xor_sync(0xffffffffu, mhi, 1));
    mhi = fmaxf(mhi, __shfl_xor_sync(0xffffffffu, mhi, 2));

    float slo = 0.f, shi = 0.f;
    #pragma unroll
    for (int ni = 0; ni < 8; ni++) {
        sacc[ni][0] = __expf(sacc[ni][0] - mlo);
        sacc[ni][1] = __expf(sacc[ni][1] - mlo);
        sacc[ni][2] = __expf(sacc[ni][2] - mhi);
        sacc[ni][3] = __expf(sacc[ni][3] - mhi);
        slo += sacc[ni][0] + sacc[ni][1];
        shi += sacc[ni][2] + sacc[ni][3];
    }
    slo += __shfl_xor_sync(0xffffffffu, slo, 1);
    slo += __shfl_xor_sync(0xffffffffu, slo, 2);
    shi += __shfl_xor_sync(0xffffffffu, shi, 1);
    shi += __shfl_xor_sync(0xffffffffu, shi, 2);
    float inv_lo = 1.f / slo, inv_hi = 1.f / shi;

    #pragma unroll
    for (int ni = 0; ni < 8; ni++) {
        *(unsigned*)&ps[wloc][i_lo][(ni << 3) + (t << 1)] = pack_h(sacc[ni][0], sacc[ni][1]);
        *(unsigned*)&ps[wloc][i_hi][(ni << 3) + (t << 1)] = pack_h(sacc[ni][2], sacc[ni][3]);
    }
    __syncwarp();

    float oacc[4][4];
    #pragma unroll
    for (int ni = 0; ni < 4; ni++)
        #pragma unroll
        for (int c = 0; c < 4; c++) oacc[ni][c] = 0.f;

    #pragma unroll
    for (int kk = 0; kk < 4; kk++) {
        int k0 = kk << 4;
        unsigned af[4];
        ldm4(af[0], af[1], af[2], af[3], ps_u + (a_off + k0) * 2);
        #pragma unroll
        for (int ni = 0; ni < 4; ni++) {
            unsigned b0, b1;
            ldm2t(b0, b1, vs_u + ((k0 + (lane & 15)) * 40 + (ni << 3)) * 2);
            asm("mma.sync.aligned.m16n8k16.row.col.f32.f16.f16.f32 "
                "{%0,%1,%2,%3}, {%4,%5,%6,%7}, {%8,%9}, {%0,%1,%2,%3};"
                : "+f"(oacc[ni][0]), "+f"(oacc[ni][1]),
                  "+f"(oacc[ni][2]), "+f"(oacc[ni][3])
                : "r"(af[0]), "r"(af[1]), "r"(af[2]), "r"(af[3]),
                  "r"(b0), "r"(b1));
        }
    }

    __half* olo = out + (size_t)(win * 64 + i_lo) * 256 + head * 32;
    __half* ohi = out + (size_t)(win * 64 + i_hi) * 256 + head * 32;
    #pragma unroll
    for (int ni = 0; ni < 4; ni++) {
        int col = (ni << 3) + (t << 1);
        *(unsigned*)(olo + col) = pack_h(oacc[ni][0] * inv_lo, oacc[ni][1] * inv_lo);
        *(unsigned*)(ohi + col) = pack_h(oacc[ni][2] * inv_hi, oacc[ni][3] * inv_hi);
    }
}

// ---------------------------------------------------------------------------
extern "C" void kernel_launch(void* const* d_in, const int* in_sizes, int n_in,
                              void* d_out, int out_size)
{
    (void)in_sizes; (void)n_in; (void)out_size;

    __half *xw, *qkv, *attnb, *h2, *mlp, *wt, *proj;
    float* rbt;
    cudaGetSymbolAddress((void**)&xw,    g_xw);
    cudaGetSymbolAddress((void**)&qkv,   g_qkv);
    cudaGetSymbolAddress((void**)&attnb, g_attn);
    cudaGetSymbolAddress((void**)&h2,    g_h2);
    cudaGetSymbolAddress((void**)&mlp,   g_mlp);
    cudaGetSymbolAddress((void**)&proj,  g_proj);
    cudaGetSymbolAddress((void**)&wt,    g_wt);
    cudaGetSymbolAddress((void**)&rbt,   g_rbt);

    cudaFuncSetAttribute(h_gemm_kernel,
                         cudaFuncAttributeMaxDynamicSharedMemorySize, GEMM_SMEM64);

    const float* x_in = (const float*)d_in[0];
    float* x = (float*)d_out;

    WtArgs wa;
    for (int blk = 0; blk < 2; blk++) {
        int base = 1 + 13 * blk;
        wa.w[blk * 4 + 0] = (const float*)d_in[base + 2];
        wa.w[blk * 4 + 1] = (const float*)d_in[base + 5];
        wa.w[blk * 4 + 2] = (const float*)d_in[base + 9];
        wa.w[blk * 4 + 3] = (const float*)d_in[base + 11];
        __half* wb = wt + blk * 786432;
        wa.o[blk * 4 + 0] = wb;
        wa.o[blk * 4 + 1] = wb + 196608;
        wa.o[blk * 4 + 2] = wb + 262144;
        wa.o[blk * 4 + 3] = wb + 524288;
    }
    wt_all_kernel<<<1536, dim3(32, 8)>>>(wa);
    rpb_gather_kernel<<<16, 256>>>((const float*)d_in[1 + 4],
                                   (const float*)d_in[1 + 13 + 4], rbt);

    for (int blk = 0; blk < 2; blk++) {
        int base = 1 + 13 * blk;
        const float* n1g  = (const float*)d_in[base + 0];
        const float* n1b  = (const float*)d_in[base + 1];
        const float* qkvb = (const float*)d_in[base + 3];
        const float* pb   = (const float*)d_in[base + 6];
        const float* n2g  = (const float*)d_in[base + 7];
        const float* n2b  = (const float*)d_in[base + 8];
        const float* f1b  = (const float*)d_in[base + 10];
        const float* f2b  = (const float*)d_in[base + 12];

        __half* wb   = wt + blk * 786432;
        __half* qkvt = wb;
        __half* pwt  = wb + 196608;
        __half* f1t  = wb + 262144;
        __half* f2t  = wb + 524288;

        int shift  = blk ? 4 : 0;
        int masked = blk;
        const float* x_cur = blk ? x : x_in;

        ln_kernel<<<8192, 256>>>(x_cur, n1g, n1b, xw, shift);
        h_gemm_kernel<<<dim3(6, 512), 256, GEMM_SMEM64>>>(
            xw, qkvt, qkvb, nullptr, qkv, 768, 256, 0, 1);
        attn_tc_kernel<<<4096, 256>>>(qkv, rbt + blk * 8 * 225, attnb, masked);
        h_gemm_kernel<<<dim3(2, 512), 256, GEMM_SMEM64>>>(
            attnb, pwt, pb, nullptr, proj, 256, 256, 0, 1);
        rev_ln_kernel<<<8192, 256>>>(proj, x_cur, x, n2g, n2b, h2, shift);
        h_gemm_kernel<<<dim3(8, 512), 256, GEMM_SMEM64>>>(
            h2, f1t, f1b, nullptr, mlp, 1024, 256, 1, 1);
        h_gemm_kernel<<<dim3(2, 512), 256, GEMM_SMEM64>>>(
            mlp, f2t, f2b, x, x, 256, 1024, 0, 0);
    }
}

// round 15
// speedup vs baseline: 1.4108x; 1.0509x over previous
#include <cuda_runtime.h>
#include <cuda_fp16.h>
#include <math.h>

// ---------------------------------------------------------------------------
// Swin: B=16, H=W=64, DIM=256, HEADS=8, HD=32, WS=8, N=64, NW=64, MLP_H=1024
// fp16 datapath, fp32 accumulate, fp32 residual stream.
// ---------------------------------------------------------------------------

#define NTOK 65536

static __device__ __half g_xw  [NTOK * 256];
static __device__ __half g_qkv [NTOK * 768];
static __device__ __half g_attn[NTOK * 256];
static __device__ __half g_h2  [NTOK * 256];
static __device__ __half g_mlp [NTOK * 1024];
static __device__ __half g_proj[NTOK * 256];
static __device__ __half g_wt  [2 * 786432];
static __device__ float  g_rbt [2 * 8 * 225];

__device__ __forceinline__ unsigned pack_h(float x, float y) {
    __half2 h = __floats2half2_rn(x, y);
    return *(unsigned*)&h;
}

// ---------------------------------------------------------------------------
// Merged weight convert+transpose for BOTH blocks: W[K][N] fp32 -> Wt[N][K] fp16
// ---------------------------------------------------------------------------
struct WtArgs {
    const float* w[8];
    __half*      o[8];
};

__global__ void wt_all_kernel(WtArgs args)
{
    __shared__ float tile[32][33];
    int b = blockIdx.x;
    int blk = b >= 768;
    b -= blk * 768;
    const float* W; __half* Wt; int K, N, nb, sel;
    if (b < 192)      { sel = 0; K = 256;  N = 768;  nb = 24; }
    else if (b < 256) { b -= 192; sel = 1; K = 256;  N = 256;  nb = 8; }
    else if (b < 512) { b -= 256; sel = 2; K = 256;  N = 1024; nb = 32; }
    else              { b -= 512; sel = 3; K = 1024; N = 256;  nb = 8; }
    W  = args.w[blk * 4 + sel];
    Wt = args.o[blk * 4 + sel];
    int n0 = (b % nb) << 5, k0 = (b / nb) << 5;
    int tx = threadIdx.x, ty = threadIdx.y;
    #pragma unroll
    for (int i = 0; i < 4; i++)
        tile[ty + i * 8][tx] = W[(size_t)(k0 + ty + i * 8) * N + n0 + tx];
    __syncthreads();
    #pragma unroll
    for (int i = 0; i < 4; i++)
        Wt[(size_t)(n0 + ty + i * 8) * K + k0 + tx] =
            __float2half_rn(tile[tx][ty + i * 8]);
}

// ---------------------------------------------------------------------------
// rpb gather: rpb[225][8] -> rbt[blk][head][225]
// ---------------------------------------------------------------------------
__global__ void rpb_gather_kernel(const float* __restrict__ rpb0,
                                  const float* __restrict__ rpb1,
                                  float* __restrict__ rbt)
{
    int blk  = blockIdx.x >> 3;
    int head = blockIdx.x & 7;
    const float* rpb = blk ? rpb1 : rpb0;
    int tid = threadIdx.x;
    if (tid < 225)
        rbt[(blk * 8 + head) * 225 + tid] = rpb[tid * 8 + head];
}

// ---------------------------------------------------------------------------
// LayerNorm (+shift + window partition), fp32 in -> fp16 out. One warp/row.
// ---------------------------------------------------------------------------
__global__ void ln_kernel(const float* __restrict__ x,
                          const float* __restrict__ gamma,
                          const float* __restrict__ beta,
                          __half* __restrict__ out,
                          int shift)
{
    int gw   = (blockIdx.x * blockDim.x + threadIdx.x) >> 5;
    int lane = threadIdx.x & 31;
    if (gw >= NTOK) return;

    int win = gw >> 6, n = gw & 63;
    int b  = win >> 6, wi = win & 63;
    int h  = (((wi >> 3) << 3) + (n >> 3) + shift) & 63;
    int w  = (((wi & 7)  << 3) + (n & 7)  + shift) & 63;
    int src = (b << 12) + (h << 6) + w;

    const float4* xr = (const float4*)x + (size_t)src * 64;
    float4 v0 = xr[lane];
    float4 v1 = xr[lane + 32];

    float s = v0.x + v0.y + v0.z + v0.w + v1.x + v1.y + v1.z + v1.w;
    #pragma unroll
    for (int o = 16; o; o >>= 1) s += __shfl_xor_sync(0xffffffffu, s, o);
    float mean = s * (1.0f / 256.0f);

    float a, ss = 0.f;
    a = v0.x - mean; ss += a * a;  a = v0.y - mean; ss += a * a;
    a = v0.z - mean; ss += a * a;  a = v0.w - mean; ss += a * a;
    a = v1.x - mean; ss += a * a;  a = v1.y - mean; ss += a * a;
    a = v1.z - mean; ss += a * a;  a = v1.w - mean; ss += a * a;
    #pragma unroll
    for (int o = 16; o; o >>= 1) ss += __shfl_xor_sync(0xffffffffu, ss, o);
    float rstd = rsqrtf(ss * (1.0f / 256.0f) + 1e-5f);

    const float4* g4 = (const float4*)gamma;
    const float4* b4 = (const float4*)beta;
    float4 g0 = g4[lane], g1 = g4[lane + 32];
    float4 c0 = b4[lane], c1 = b4[lane + 32];

    unsigned* o32 = (unsigned*)(out + (size_t)gw * 256);
    uint2 r0, r1;
    r0.x = pack_h((v0.x - mean) * rstd * g0.x + c0.x,
                  (v0.y - mean) * rstd * g0.y + c0.y);
    r0.y = pack_h((v0.z - mean) * rstd * g0.z + c0.z,
                  (v0.w - mean) * rstd * g0.w + c0.w);
    r1.x = pack_h((v1.x - mean) * rstd * g1.x + c1.x,
                  (v1.y - mean) * rstd * g1.y + c1.y);
    r1.y = pack_h((v1.z - mean) * rstd * g1.z + c1.z,
                  (v1.w - mean) * rstd * g1.w + c1.w);
    *(uint2*)(o32 + lane * 2)      = r0;
    *(uint2*)(o32 + 64 + lane * 2) = r1;
}

// ---------------------------------------------------------------------------
// Fused window-reverse + un-shift + residual + LayerNorm2.
// ---------------------------------------------------------------------------
__global__ void rev_ln_kernel(const __half* __restrict__ proj,
                              const float* __restrict__ x_src,
                              float* __restrict__ x_dst,
                              const float* __restrict__ gamma,
                              const float* __restrict__ beta,
                              __half* __restrict__ h2,
                              int shift)
{
    int gw   = (blockIdx.x * blockDim.x + threadIdx.x) >> 5;
    int lane = threadIdx.x & 31;
    if (gw >= NTOK) return;

    int b = gw >> 12, h = (gw >> 6) & 63, w = gw & 63;
    int hh = (h - shift) & 63, ww = (w - shift) & 63;
    int row = ((b << 6) + ((hh >> 3) << 3) + (ww >> 3)) * 64
            + ((hh & 7) << 3) + (ww & 7);

    const __half2* pr = (const __half2*)(proj + (size_t)row * 256);
    const float4* xr = (const float4*)x_src + (size_t)gw * 64;
    float4 v0 = xr[lane],      v1 = xr[lane + 32];
    __half2 pa = pr[lane * 2],      pb = pr[lane * 2 + 1];
    __half2 pc = pr[64 + lane * 2], pd = pr[64 + lane * 2 + 1];
    float2 fa = __half22float2(pa), fb = __half22float2(pb);
    float2 fc = __half22float2(pc), fd = __half22float2(pd);
    v0.x += fa.x; v0.y += fa.y; v0.z += fb.x; v0.w += fb.y;
    v1.x += fc.x; v1.y += fc.y; v1.z += fd.x; v1.w += fd.y;

    float4* xo = (float4*)x_dst + (size_t)gw * 64;
    xo[lane]      = v0;
    xo[lane + 32] = v1;

    float s = v0.x + v0.y + v0.z + v0.w + v1.x + v1.y + v1.z + v1.w;
    #pragma unroll
    for (int o = 16; o; o >>= 1) s += __shfl_xor_sync(0xffffffffu, s, o);
    float mean = s * (1.0f / 256.0f);

    float a, ss = 0.f;
    a = v0.x - mean; ss += a * a;  a = v0.y - mean; ss += a * a;
    a = v0.z - mean; ss += a * a;  a = v0.w - mean; ss += a * a;
    a = v1.x - mean; ss += a * a;  a = v1.y - mean; ss += a * a;
    a = v1.z - mean; ss += a * a;  a = v1.w - mean; ss += a * a;
    #pragma unroll
    for (int o = 16; o; o >>= 1) ss += __shfl_xor_sync(0xffffffffu, ss, o);
    float rstd = rsqrtf(ss * (1.0f / 256.0f) + 1e-5f);

    const float4* g4 = (const float4*)gamma;
    const float4* b4 = (const float4*)beta;
    float4 g0 = g4[lane], g1 = g4[lane + 32];
    float4 c0 = b4[lane], c1 = b4[lane + 32];

    unsigned* o32 = (unsigned*)(h2 + (size_t)gw * 256);
    uint2 r0, r1;
    r0.x = pack_h((v0.x - mean) * rstd * g0.x + c0.x,
                  (v0.y - mean) * rstd * g0.y + c0.y);
    r0.y = pack_h((v0.z - mean) * rstd * g0.z + c0.z,
                  (v0.w - mean) * rstd * g0.w + c0.w);
    r1.x = pack_h((v1.x - mean) * rstd * g1.x + c1.x,
                  (v1.y - mean) * rstd * g1.y + c1.y);
    r1.y = pack_h((v1.z - mean) * rstd * g1.z + c1.z,
                  (v1.w - mean) * rstd * g1.w + c1.w);
    *(uint2*)(o32 + lane * 2)      = r0;
    *(uint2*)(o32 + 64 + lane * 2) = r1;
}

// ---------------------------------------------------------------------------
// fp16 tensor-core GEMM, BK=64 (R14 winner) with prefetch moved off the
// barrier edge and a fully-unrolled K=256 path.
// ---------------------------------------------------------------------------
#define HS64 72
#define STG64 (128 * HS64)
#define GEMM_SMEM64 (3 * 2 * STG64 * 2)    // 110592 bytes

__device__ __forceinline__ void cp16(void* s, const void* g) {
    unsigned sa = (unsigned)__cvta_generic_to_shared(s);
    asm volatile("cp.async.cg.shared.global [%0], [%1], 16;" :: "r"(sa), "l"(g));
}

__device__ __forceinline__ void ldm4(unsigned& r0, unsigned& r1,
                                     unsigned& r2, unsigned& r3, unsigned addr) {
    asm volatile("ldmatrix.sync.aligned.m8n8.x4.shared.b16 {%0,%1,%2,%3}, [%4];"
                 : "=r"(r0), "=r"(r1), "=r"(r2), "=r"(r3) : "r"(addr));
}

__device__ __forceinline__ void ldm2t(unsigned& r0, unsigned& r1, unsigned addr) {
    asm volatile("ldmatrix.sync.aligned.m8n8.x2.trans.shared.b16 {%0,%1}, [%2];"
                 : "=r"(r0), "=r"(r1) : "r"(addr));
}

__global__ void __launch_bounds__(256, 2)
h_gemm_kernel(const __half* __restrict__ A,
              const __half* __restrict__ Bt,
              const float* __restrict__ bias,
              const float* __restrict__ R,
              void* __restrict__ Cv,
              int N, int K, int act, int out_h16)
{
    extern __shared__ __half smem[];
    __half* As = smem;
    __half* Bs = smem + 3 * STG64;

    int tid  = threadIdx.x;
    int bm   = blockIdx.y << 7;
    int bn   = blockIdx.x << 7;
    int wid  = tid >> 5, lane = tid & 31;
    int wm   = (wid & 3) << 5;
    int wn   = (wid >> 2) << 6;
    int g    = lane >> 2, t = lane & 3;

    float acc[2][8][4];
    #pragma unroll
    for (int mi = 0; mi < 2; mi++)
        #pragma unroll
        for (int ni = 0; ni < 8; ni++)
            #pragma unroll
            for (int c = 0; c < 4; c++) acc[mi][ni][c] = 0.f;

    int a_m = tid >> 3;
    int a_k = (tid & 7) << 3;
    int iters = K >> 6;

    unsigned as_u = (unsigned)__cvta_generic_to_shared(As);
    unsigned bs_u = (unsigned)__cvta_generic_to_shared(Bs);
    int a_off = (wm + (lane & 15)) * HS64 + ((lane >> 4) << 3);
    int b_off = (wn + ((lane >> 4) << 3) + (lane & 7)) * HS64
              + (((lane >> 3) & 1) << 3);

    #define LOAD_STAGE64(si, kb)                                                \
    {                                                                           \
        __half* as = As + (si) * STG64;                                         \
        __half* bs = Bs + (si) * STG64;                                         \
        _Pragma("unroll")                                                       \
        for (int u = 0; u < 4; u++) {                                           \
            int row = a_m + (u << 5);                                           \
            cp16(as + row * HS64 + a_k,                                         \
                 A + (size_t)(bm + row) * K + (kb) + a_k);                      \
            cp16(bs + row * HS64 + a_k,                                         \
                 Bt + (size_t)(bn + row) * K + (kb) + a_k);                     \
        }                                                                       \
        asm volatile("cp.async.commit_group;");                                 \
    }

    // one kk sub-step (16 K-halves) of the 64-wide chunk
    #define KSTEP(abase, bbase, k0)                                             \
    {                                                                           \
        unsigned af[2][4], bf[8][2];                                            \
        _Pragma("unroll")                                                       \
        for (int mi = 0; mi < 2; mi++)                                          \
            ldm4(af[mi][0], af[mi][1], af[mi][2], af[mi][3],                    \
                 (abase) + (a_off + (mi << 4) * HS64 + (k0)) * 2);              \
        _Pragma("unroll")                                                       \
        for (int p = 0; p < 4; p++)                                             \
            ldm4(bf[2 * p][0], bf[2 * p][1], bf[2 * p + 1][0], bf[2 * p + 1][1],\
                 (bbase) + (b_off + (p << 4) * HS64 + (k0)) * 2);               \
        _Pragma("unroll")                                                       \
        for (int mi = 0; mi < 2; mi++)                                          \
            _Pragma("unroll")                                                   \
            for (int ni = 0; ni < 8; ni++) {                                    \
                asm("mma.sync.aligned.m16n8k16.row.col.f32.f16.f16.f32 "        \
                    "{%0,%1,%2,%3}, {%4,%5,%6,%7}, {%8,%9}, {%0,%1,%2,%3};"     \
                    : "+f"(acc[mi][ni][0]), "+f"(acc[mi][ni][1]),               \
                      "+f"(acc[mi][ni][2]), "+f"(acc[mi][ni][3])                \
                    : "r"(af[mi][0]), "r"(af[mi][1]), "r"(af[mi][2]),           \
                      "r"(af[mi][3]), "r"(bf[ni][0]), "r"(bf[ni][1]));          \
            }                                                                   \
    }

    LOAD_STAGE64(0, 0)
    LOAD_STAGE64(1, 64)

    if (K == 256) {
        // fully unrolled 4 iterations; prefetch issued after first kk sub-step
        #pragma unroll
        for (int i = 0; i < 4; i++) {
            if (i < 2)      asm volatile("cp.async.wait_group 1;");
            else if (i == 2) asm volatile("cp.async.wait_group 1;");
            else             asm volatile("cp.async.wait_group 0;");
            __syncthreads();

            unsigned abase = as_u + ((i % 3) * STG64) * 2;
            unsigned bbase = bs_u + ((i % 3) * STG64) * 2;
            KSTEP(abase, bbase, 0)
            if (i < 2) LOAD_STAGE64((i + 2) % 3, (i + 2) << 6)
            KSTEP(abase, bbase, 16)
            KSTEP(abase, bbase, 32)
            KSTEP(abase, bbase, 48)
        }
    } else {
        for (int i = 0; i < iters; i++) {
            if (i + 1 < iters) asm volatile("cp.async.wait_group 1;");
            else               asm volatile("cp.async.wait_group 0;");
            __syncthreads();

            unsigned abase = as_u + ((i % 3) * STG64) * 2;
            unsigned bbase = bs_u + ((i % 3) * STG64) * 2;
            KSTEP(abase, bbase, 0)
            if (i + 2 < iters) LOAD_STAGE64((i + 2) % 3, (i + 2) << 6)
            KSTEP(abase, bbase, 16)
            KSTEP(abase, bbase, 32)
            KSTEP(abase, bbase, 48)
        }
    }

    #pragma unroll
    for (int mi = 0; mi < 2; mi++) {
        int row0 = bm + wm + (mi << 4) + g;
        #pragma unroll
        for (int ni = 0; ni < 8; ni++) {
            int col = bn + wn + (ni << 3) + (t << 1);
            float2 bb = *(const float2*)(bias + col);
            float2 u, v;
            u.x = acc[mi][ni][0] + bb.x;
            u.y = acc[mi][ni][1] + bb.y;
            v.x = acc[mi][ni][2] + bb.x;
            v.y = acc[mi][ni][3] + bb.y;
            if (act) {
                u.x = 0.5f * u.x * (1.f + erff(u.x * 0.70710678118654752f));
                u.y = 0.5f * u.y * (1.f + erff(u.y * 0.70710678118654752f));
                v.x = 0.5f * v.x * (1.f + erff(v.x * 0.70710678118654752f));
                v.y = 0.5f * v.y * (1.f + erff(v.y * 0.70710678118654752f));
            }
            size_t o0 = (size_t)row0 * N + col;
            size_t o1 = (size_t)(row0 + 8) * N + col;
            if (out_h16) {
                unsigned* C = (unsigned*)Cv;
                C[o0 >> 1] = pack_h(u.x, u.y);
                C[o1 >> 1] = pack_h(v.x, v.y);
            } else {
                float* C = (float*)Cv;
                if (R) {
                    float2 r0 = *(const float2*)(R + o0);
                    float2 r1 = *(const float2*)(R + o1);
                    u.x += r0.x; u.y += r0.y; v.x += r1.x; v.y += r1.y;
                }
                *(float2*)(C + o0) = u;
                *(float2*)(C + o1) = v;
            }
        }
    }
}

// ---------------------------------------------------------------------------
// fp16 tensor-core window attention (R14): 2 windows per 256-thread CTA.
// ---------------------------------------------------------------------------
__global__ void __launch_bounds__(256)
attn_tc_kernel(const __half* __restrict__ qkv,
               const float* __restrict__ rbt,
               __half* __restrict__ out,
               int masked)
{
    __shared__ __half ks[2][64][40];
    __shared__ __half vs[2][64][40];
    __shared__ __half ps[2][64][72];
    __shared__ float rb[232];

    const float SCALE = 0.17677669529663687f;

    int idx  = blockIdx.x;
    int head = idx & 7;
    int wp   = idx >> 3;
    int tid  = threadIdx.x;
    int warp = tid >> 5, lane = tid & 31;
    int g = lane >> 2, t = lane & 3;

    {
        int sw   = tid >> 7;
        int stid = tid & 127;
        int tok  = stid >> 1;
        int half = (stid & 1) << 4;
        const __half* bq = qkv + (size_t)((wp * 2 + sw) * 64 + tok) * 768 + head * 32 + half;
        uint4 qa = *(const uint4*)(bq);
        uint4 qb = *(const uint4*)(bq + 8);
        *(uint4*)&ps[sw][tok][half]     = qa;
        *(uint4*)&ps[sw][tok][half + 8] = qb;
        uint4 ka = *(const uint4*)(bq + 256);
        uint4 kb = *(const uint4*)(bq + 264);
        *(uint4*)&ks[sw][tok][half]     = ka;
        *(uint4*)&ks[sw][tok][half + 8] = kb;
        uint4 va = *(const uint4*)(bq + 512);
        uint4 vb = *(const uint4*)(bq + 520);
        *(uint4*)&vs[sw][tok][half]     = va;
        *(uint4*)&vs[sw][tok][half + 8] = vb;
    }
    if (tid < 225) rb[tid] = rbt[head * 225 + tid];
    __syncthreads();

    int wloc = warp >> 2;
    int win  = wp * 2 + wloc;
    int wm   = (warp & 3) << 4;
    int i_lo = wm + g, i_hi = i_lo + 8;

    unsigned ks_u = (unsigned)__cvta_generic_to_shared(&ks[wloc][0][0]);
    unsigned vs_u = (unsigned)__cvta_generic_to_shared(&vs[wloc][0][0]);
    unsigned ps_u = (unsigned)__cvta_generic_to_shared(&ps[wloc][0][0]);
    int b_off = (((lane >> 4) << 3) + (lane & 7)) * 40 + (((lane >> 3) & 1) << 3);
    int a_off = (wm + (lane & 15)) * 72 + ((lane >> 4) << 3);

    float sacc[8][4];
    #pragma unroll
    for (int ni = 0; ni < 8; ni++)
        #pragma unroll
        for (int c = 0; c < 4; c++) sacc[ni][c] = 0.f;

    #pragma unroll
    for (int kk = 0; kk < 2; kk++) {
        int k0 = kk << 4;
        unsigned qf[4];
        ldm4(qf[0], qf[1], qf[2], qf[3], ps_u + (a_off + k0) * 2);
        unsigned bf[8][2];
        #pragma unroll
        for (int p = 0; p < 4; p++)
            ldm4(bf[2 * p][0], bf[2 * p][1], bf[2 * p + 1][0], bf[2 * p + 1][1],
                 ks_u + (b_off + (p << 4) * 40 + k0) * 2);
        #pragma unroll
        for (int ni = 0; ni < 8; ni++) {
            asm("mma.sync.aligned.m16n8k16.row.col.f32.f16.f16.f32 "
                "{%0,%1,%2,%3}, {%4,%5,%6,%7}, {%8,%9}, {%0,%1,%2,%3};"
                : "+f"(sacc[ni][0]), "+f"(sacc[ni][1]),
                  "+f"(sacc[ni][2]), "+f"(sacc[ni][3])
                : "r"(qf[0]), "r"(qf[1]), "r"(qf[2]), "r"(qf[3]),
                  "r"(bf[ni][0]), "r"(bf[ni][1]));
        }
    }

    int yi0 = i_lo >> 3, xi0 = i_lo & 7;
    int yi1 = i_hi >> 3, xi1 = i_hi & 7;
    int wi = win & 63;
    int whbase = (wi >> 3) << 3;
    int wwbase = (wi & 7) << 3;
    int reg0 = 0, reg1 = 0;
    if (masked) {
        int h0 = whbase + yi0, w0 = wwbase + xi0;
        int h1 = whbase + yi1, w1 = wwbase + xi1;
        reg0 = ((h0 >= 56) + (h0 >= 60)) * 3 + (w0 >= 56) + (w0 >= 60);
        reg1 = ((h1 >= 56) + (h1 >= 60)) * 3 + (w1 >= 56) + (w1 >= 60);
    }
    #pragma unroll
    for (int ni = 0; ni < 8; ni++) {
        #pragma unroll
        for (int c = 0; c < 2; c++) {
            int j = (ni << 3) + (t << 1) + c;
            int yj = j >> 3, xj = j & 7;
            sacc[ni][c]     = sacc[ni][c]     * SCALE + rb[(yi0 - yj + 7) * 15 + (xi0 - xj + 7)];
            sacc[ni][2 + c] = sacc[ni][2 + c] * SCALE + rb[(yi1 - yj + 7) * 15 + (xi1 - xj + 7)];
            if (masked) {
                int hj = whbase + yj, wj = wwbase + xj;
                int regj = ((hj >= 56) + (hj >= 60)) * 3 + (wj >= 56) + (wj >= 60);
                if (regj != reg0) sacc[ni][c]     -= 100.f;
                if (regj != reg1) sacc[ni][2 + c] -= 100.f;
            }
        }
    }

    float mlo = -1e30f, mhi = -1e30f;
    #pragma unroll
    for (int ni = 0; ni < 8; ni++) {
        mlo = fmaxf(mlo, fmaxf(sacc[ni][0], sacc[ni][1]));
        mhi = fmaxf(mhi, fmaxf(sacc[ni][2], sacc[ni][3]));
    }
    mlo = fmaxf(mlo, __shfl_xor_sync(0xffffffffu, mlo, 1));
    mlo = fmaxf(mlo, __shfl_xor_sync(0xffffffffu, mlo, 2));
    mhi = fmaxf(mhi, __shfl_xor_sync(0xffffffffu, mhi, 1));
    mhi = fmaxf(mhi, __shfl_xor_sync(0xffffffffu, mhi, 2));

    float slo = 0.f, shi = 0.f;
    #pragma unroll
    for (int ni = 0; ni < 8; ni++) {
        sacc[ni][0] = __expf(sacc[ni][0] - mlo);
        sacc[ni][1] = __expf(sacc[ni][1] - mlo);
        sacc[ni][2] = __expf(sacc[ni][2] - mhi);
        sacc[ni][3] = __expf(sacc[ni][3] - mhi);
        slo += sacc[ni][0] + sacc[ni][1];
        shi += sacc[ni][2] + sacc[ni][3];
    }
    slo += __shfl_xor_sync(0xffffffffu, slo, 1);
    slo += __shfl_xor_sync(0xffffffffu, slo, 2);
    shi += __shfl_xor_sync(0xffffffffu, shi, 1);
    shi += __shfl_xor_sync(0xffffffffu, shi, 2);
    float inv_lo = 1.f / slo, inv_hi = 1.f / shi;

    #pragma unroll
    for (int ni = 0; ni < 8; ni++) {
        *(unsigned*)&ps[wloc][i_lo][(ni << 3) + (t << 1)] = pack_h(sacc[ni][0], sacc[ni][1]);
        *(unsigned*)&ps[wloc][i_hi][(ni << 3) + (t << 1)] = pack_h(sacc[ni][2], sacc[ni][3]);
    }
    __syncwarp();

    float oacc[4][4];
    #pragma unroll
    for (int ni = 0; ni < 4; ni++)
        #pragma unroll
        for (int c = 0; c < 4; c++) oacc[ni][c] = 0.f;

    #pragma unroll
    for (int kk = 0; kk < 4; kk++) {
        int k0 = kk << 4;
        unsigned af[4];
        ldm4(af[0], af[1], af[2], af[3], ps_u + (a_off + k0) * 2);
        #pragma unroll
        for (int ni = 0; ni < 4; ni++) {
            unsigned b0, b1;
            ldm2t(b0, b1, vs_u + ((k0 + (lane & 15)) * 40 + (ni << 3)) * 2);
            asm("mma.sync.aligned.m16n8k16.row.col.f32.f16.f16.f32 "
                "{%0,%1,%2,%3}, {%4,%5,%6,%7}, {%8,%9}, {%0,%1,%2,%3};"
                : "+f"(oacc[ni][0]), "+f"(oacc[ni][1]),
                  "+f"(oacc[ni][2]), "+f"(oacc[ni][3])
                : "r"(af[0]), "r"(af[1]), "r"(af[2]), "r"(af[3]),
                  "r"(b0), "r"(b1));
        }
    }

    __half* olo = out + (size_t)(win * 64 + i_lo) * 256 + head * 32;
    __half* ohi = out + (size_t)(win * 64 + i_hi) * 256 + head * 32;
    #pragma unroll
    for (int ni = 0; ni < 4; ni++) {
        int col = (ni << 3) + (t << 1);
        *(unsigned*)(olo + col) = pack_h(oacc[ni][0] * inv_lo, oacc[ni][1] * inv_lo);
        *(unsigned*)(ohi + col) = pack_h(oacc[ni][2] * inv_hi, oacc[ni][3] * inv_hi);
    }
}

// ---------------------------------------------------------------------------
extern "C" void kernel_launch(void* const* d_in, const int* in_sizes, int n_in,
                              void* d_out, int out_size)
{
    (void)in_sizes; (void)n_in; (void)out_size;

    __half *xw, *qkv, *attnb, *h2, *mlp, *wt, *proj;
    float* rbt;
    cudaGetSymbolAddress((void**)&xw,    g_xw);
    cudaGetSymbolAddress((void**)&qkv,   g_qkv);
    cudaGetSymbolAddress((void**)&attnb, g_attn);
    cudaGetSymbolAddress((void**)&h2,    g_h2);
    cudaGetSymbolAddress((void**)&mlp,   g_mlp);
    cudaGetSymbolAddress((void**)&proj,  g_proj);
    cudaGetSymbolAddress((void**)&wt,    g_wt);
    cudaGetSymbolAddress((void**)&rbt,   g_rbt);

    cudaFuncSetAttribute(h_gemm_kernel,
                         cudaFuncAttributeMaxDynamicSharedMemorySize, GEMM_SMEM64);

    const float* x_in = (const float*)d_in[0];
    float* x = (float*)d_out;

    WtArgs wa;
    for (int blk = 0; blk < 2; blk++) {
        int base = 1 + 13 * blk;
        wa.w[blk * 4 + 0] = (const float*)d_in[base + 2];
        wa.w[blk * 4 + 1] = (const float*)d_in[base + 5];
        wa.w[blk * 4 + 2] = (const float*)d_in[base + 9];
        wa.w[blk * 4 + 3] = (const float*)d_in[base + 11];
        __half* wb = wt + blk * 786432;
        wa.o[blk * 4 + 0] = wb;
        wa.o[blk * 4 + 1] = wb + 196608;
        wa.o[blk * 4 + 2] = wb + 262144;
        wa.o[blk * 4 + 3] = wb + 524288;
    }
    wt_all_kernel<<<1536, dim3(32, 8)>>>(wa);
    rpb_gather_kernel<<<16, 256>>>((const float*)d_in[1 + 4],
                                   (const float*)d_in[1 + 13 + 4], rbt);

    for (int blk = 0; blk < 2; blk++) {
        int base = 1 + 13 * blk;
        const float* n1g  = (const float*)d_in[base + 0];
        const float* n1b  = (const float*)d_in[base + 1];
        const float* qkvb = (const float*)d_in[base + 3];
        const float* pb   = (const float*)d_in[base + 6];
        const float* n2g  = (const float*)d_in[base + 7];
        const float* n2b  = (const float*)d_in[base + 8];
        const float* f1b  = (const float*)d_in[base + 10];
        const float* f2b  = (const float*)d_in[base + 12];

        __half* wb   = wt + blk * 786432;
        __half* qkvt = wb;
        __half* pwt  = wb + 196608;
        __half* f1t  = wb + 262144;
        __half* f2t  = wb + 524288;

        int shift  = blk ? 4 : 0;
        int masked = blk;
        const float* x_cur = blk ? x : x_in;

        ln_kernel<<<8192, 256>>>(x_cur, n1g, n1b, xw, shift);
        h_gemm_kernel<<<dim3(6, 512), 256, GEMM_SMEM64>>>(
            xw, qkvt, qkvb, nullptr, qkv, 768, 256, 0, 1);
        attn_tc_kernel<<<4096, 256>>>(qkv, rbt + blk * 8 * 225, attnb, masked);
        h_gemm_kernel<<<dim3(2, 512), 256, GEMM_SMEM64>>>(
            attnb, pwt, pb, nullptr, proj, 256, 256, 0, 1);
        rev_ln_kernel<<<8192, 256>>>(proj, x_cur, x, n2g, n2b, h2, shift);
        h_gemm_kernel<<<dim3(8, 512), 256, GEMM_SMEM64>>>(
            h2, f1t, f1b, nullptr, mlp, 1024, 256, 1, 1);
        h_gemm_kernel<<<dim3(2, 512), 256, GEMM_SMEM64>>>(
            mlp, f2t, f2b, x, x, 256, 1024, 0, 0);
    }
}

// round 16
// speedup vs baseline: 1.4826x; 1.0509x over previous
#include <cuda_runtime.h>
#include <cuda_fp16.h>
#include <math.h>

// ---------------------------------------------------------------------------
// Swin: B=16, H=W=64, DIM=256, HEADS=8, HD=32, WS=8, N=64, NW=64, MLP_H=1024
// fp16 datapath, fp32 accumulate, fp32 residual stream.
// ---------------------------------------------------------------------------

#define NTOK 65536

static __device__ __half g_xw  [NTOK * 256];
static __device__ __half g_qkv [NTOK * 768];
static __device__ __half g_attn[NTOK * 256];
static __device__ __half g_h2  [NTOK * 256];
static __device__ __half g_mlp [NTOK * 1024];
static __device__ __half g_proj[NTOK * 256];
static __device__ __half g_wt  [2 * 786432];
static __device__ float  g_rbt [2 * 8 * 225];

__device__ __forceinline__ unsigned pack_h(float x, float y) {
    __half2 h = __floats2half2_rn(x, y);
    return *(unsigned*)&h;
}

// ---------------------------------------------------------------------------
// Merged weight convert+transpose for BOTH blocks: W[K][N] fp32 -> Wt[N][K] fp16
// ---------------------------------------------------------------------------
struct WtArgs {
    const float* w[8];
    __half*      o[8];
};

__global__ void wt_all_kernel(WtArgs args)
{
    __shared__ float tile[32][33];
    int b = blockIdx.x;
    int blk = b >= 768;
    b -= blk * 768;
    const float* W; __half* Wt; int K, N, nb, sel;
    if (b < 192)      { sel = 0; K = 256;  N = 768;  nb = 24; }
    else if (b < 256) { b -= 192; sel = 1; K = 256;  N = 256;  nb = 8; }
    else if (b < 512) { b -= 256; sel = 2; K = 256;  N = 1024; nb = 32; }
    else              { b -= 512; sel = 3; K = 1024; N = 256;  nb = 8; }
    W  = args.w[blk * 4 + sel];
    Wt = args.o[blk * 4 + sel];
    int n0 = (b % nb) << 5, k0 = (b / nb) << 5;
    int tx = threadIdx.x, ty = threadIdx.y;
    #pragma unroll
    for (int i = 0; i < 4; i++)
        tile[ty + i * 8][tx] = W[(size_t)(k0 + ty + i * 8) * N + n0 + tx];
    __syncthreads();
    #pragma unroll
    for (int i = 0; i < 4; i++)
        Wt[(size_t)(n0 + ty + i * 8) * K + k0 + tx] =
            __float2half_rn(tile[tx][ty + i * 8]);
}

// ---------------------------------------------------------------------------
// rpb gather: rpb[225][8] -> rbt[blk][head][225]
// ---------------------------------------------------------------------------
__global__ void rpb_gather_kernel(const float* __restrict__ rpb0,
                                  const float* __restrict__ rpb1,
                                  float* __restrict__ rbt)
{
    int blk  = blockIdx.x >> 3;
    int head = blockIdx.x & 7;
    const float* rpb = blk ? rpb1 : rpb0;
    int tid = threadIdx.x;
    if (tid < 225)
        rbt[(blk * 8 + head) * 225 + tid] = rpb[tid * 8 + head];
}

// ---------------------------------------------------------------------------
// LayerNorm (+shift + window partition), fp32 in -> fp16 out. One warp/row.
// ---------------------------------------------------------------------------
__global__ void ln_kernel(const float* __restrict__ x,
                          const float* __restrict__ gamma,
                          const float* __restrict__ beta,
                          __half* __restrict__ out,
                          int shift)
{
    int gw   = (blockIdx.x * blockDim.x + threadIdx.x) >> 5;
    int lane = threadIdx.x & 31;
    if (gw >= NTOK) return;

    int win = gw >> 6, n = gw & 63;
    int b  = win >> 6, wi = win & 63;
    int h  = (((wi >> 3) << 3) + (n >> 3) + shift) & 63;
    int w  = (((wi & 7)  << 3) + (n & 7)  + shift) & 63;
    int src = (b << 12) + (h << 6) + w;

    const float4* xr = (const float4*)x + (size_t)src * 64;
    float4 v0 = xr[lane];
    float4 v1 = xr[lane + 32];

    float s = v0.x + v0.y + v0.z + v0.w + v1.x + v1.y + v1.z + v1.w;
    #pragma unroll
    for (int o = 16; o; o >>= 1) s += __shfl_xor_sync(0xffffffffu, s, o);
    float mean = s * (1.0f / 256.0f);

    float a, ss = 0.f;
    a = v0.x - mean; ss += a * a;  a = v0.y - mean; ss += a * a;
    a = v0.z - mean; ss += a * a;  a = v0.w - mean; ss += a * a;
    a = v1.x - mean; ss += a * a;  a = v1.y - mean; ss += a * a;
    a = v1.z - mean; ss += a * a;  a = v1.w - mean; ss += a * a;
    #pragma unroll
    for (int o = 16; o; o >>= 1) ss += __shfl_xor_sync(0xffffffffu, ss, o);
    float rstd = rsqrtf(ss * (1.0f / 256.0f) + 1e-5f);

    const float4* g4 = (const float4*)gamma;
    const float4* b4 = (const float4*)beta;
    float4 g0 = g4[lane], g1 = g4[lane + 32];
    float4 c0 = b4[lane], c1 = b4[lane + 32];

    unsigned* o32 = (unsigned*)(out + (size_t)gw * 256);
    uint2 r0, r1;
    r0.x = pack_h((v0.x - mean) * rstd * g0.x + c0.x,
                  (v0.y - mean) * rstd * g0.y + c0.y);
    r0.y = pack_h((v0.z - mean) * rstd * g0.z + c0.z,
                  (v0.w - mean) * rstd * g0.w + c0.w);
    r1.x = pack_h((v1.x - mean) * rstd * g1.x + c1.x,
                  (v1.y - mean) * rstd * g1.y + c1.y);
    r1.y = pack_h((v1.z - mean) * rstd * g1.z + c1.z,
                  (v1.w - mean) * rstd * g1.w + c1.w);
    *(uint2*)(o32 + lane * 2)      = r0;
    *(uint2*)(o32 + 64 + lane * 2) = r1;
}

// ---------------------------------------------------------------------------
// Fused window-reverse + un-shift + residual + LayerNorm2.
// ---------------------------------------------------------------------------
__global__ void rev_ln_kernel(const __half* __restrict__ proj,
                              const float* __restrict__ x_src,
                              float* __restrict__ x_dst,
                              const float* __restrict__ gamma,
                              const float* __restrict__ beta,
                              __half* __restrict__ h2,
                              int shift)
{
    int gw   = (blockIdx.x * blockDim.x + threadIdx.x) >> 5;
    int lane = threadIdx.x & 31;
    if (gw >= NTOK) return;

    int b = gw >> 12, h = (gw >> 6) & 63, w = gw & 63;
    int hh = (h - shift) & 63, ww = (w - shift) & 63;
    int row = ((b << 6) + ((hh >> 3) << 3) + (ww >> 3)) * 64
            + ((hh & 7) << 3) + (ww & 7);

    const __half2* pr = (const __half2*)(proj + (size_t)row * 256);
    const float4* xr = (const float4*)x_src + (size_t)gw * 64;
    float4 v0 = xr[lane],      v1 = xr[lane + 32];
    __half2 pa = pr[lane * 2],      pb = pr[lane * 2 + 1];
    __half2 pc = pr[64 + lane * 2], pd = pr[64 + lane * 2 + 1];
    float2 fa = __half22float2(pa), fb = __half22float2(pb);
    float2 fc = __half22float2(pc), fd = __half22float2(pd);
    v0.x += fa.x; v0.y += fa.y; v0.z += fb.x; v0.w += fb.y;
    v1.x += fc.x; v1.y += fc.y; v1.z += fd.x; v1.w += fd.y;

    float4* xo = (float4*)x_dst + (size_t)gw * 64;
    xo[lane]      = v0;
    xo[lane + 32] = v1;

    float s = v0.x + v0.y + v0.z + v0.w + v1.x + v1.y + v1.z + v1.w;
    #pragma unroll
    for (int o = 16; o; o >>= 1) s += __shfl_xor_sync(0xffffffffu, s, o);
    float mean = s * (1.0f / 256.0f);

    float a, ss = 0.f;
    a = v0.x - mean; ss += a * a;  a = v0.y - mean; ss += a * a;
    a = v0.z - mean; ss += a * a;  a = v0.w - mean; ss += a * a;
    a = v1.x - mean; ss += a * a;  a = v1.y - mean; ss += a * a;
    a = v1.z - mean; ss += a * a;  a = v1.w - mean; ss += a * a;
    #pragma unroll
    for (int o = 16; o; o >>= 1) ss += __shfl_xor_sync(0xffffffffu, ss, o);
    float rstd = rsqrtf(ss * (1.0f / 256.0f) + 1e-5f);

    const float4* g4 = (const float4*)gamma;
    const float4* b4 = (const float4*)beta;
    float4 g0 = g4[lane], g1 = g4[lane + 32];
    float4 c0 = b4[lane], c1 = b4[lane + 32];

    unsigned* o32 = (unsigned*)(h2 + (size_t)gw * 256);
    uint2 r0, r1;
    r0.x = pack_h((v0.x - mean) * rstd * g0.x + c0.x,
                  (v0.y - mean) * rstd * g0.y + c0.y);
    r0.y = pack_h((v0.z - mean) * rstd * g0.z + c0.z,
                  (v0.w - mean) * rstd * g0.w + c0.w);
    r1.x = pack_h((v1.x - mean) * rstd * g1.x + c1.x,
                  (v1.y - mean) * rstd * g1.y + c1.y);
    r1.y = pack_h((v1.z - mean) * rstd * g1.z + c1.z,
                  (v1.w - mean) * rstd * g1.w + c1.w);
    *(uint2*)(o32 + lane * 2)      = r0;
    *(uint2*)(o32 + 64 + lane * 2) = r1;
}

// ---------------------------------------------------------------------------
// fp16 tensor-core GEMM, BK=64 (R15 winner) + unrolled K=1024 path and
// split A/B prefetch across two mma windows.
// ---------------------------------------------------------------------------
#define HS64 72
#define STG64 (128 * HS64)
#define GEMM_SMEM64 (3 * 2 * STG64 * 2)    // 110592 bytes

__device__ __forceinline__ void cp16(void* s, const void* g) {
    unsigned sa = (unsigned)__cvta_generic_to_shared(s);
    asm volatile("cp.async.cg.shared.global [%0], [%1], 16;" :: "r"(sa), "l"(g));
}

__device__ __forceinline__ void ldm4(unsigned& r0, unsigned& r1,
                                     unsigned& r2, unsigned& r3, unsigned addr) {
    asm volatile("ldmatrix.sync.aligned.m8n8.x4.shared.b16 {%0,%1,%2,%3}, [%4];"
                 : "=r"(r0), "=r"(r1), "=r"(r2), "=r"(r3) : "r"(addr));
}

__device__ __forceinline__ void ldm2t(unsigned& r0, unsigned& r1, unsigned addr) {
    asm volatile("ldmatrix.sync.aligned.m8n8.x2.trans.shared.b16 {%0,%1}, [%2];"
                 : "=r"(r0), "=r"(r1) : "r"(addr));
}

__global__ void __launch_bounds__(256, 2)
h_gemm_kernel(const __half* __restrict__ A,
              const __half* __restrict__ Bt,
              const float* __restrict__ bias,
              const float* __restrict__ R,
              void* __restrict__ Cv,
              int N, int K, int act, int out_h16)
{
    extern __shared__ __half smem[];
    __half* As = smem;
    __half* Bs = smem + 3 * STG64;

    int tid  = threadIdx.x;
    int bm   = blockIdx.y << 7;
    int bn   = blockIdx.x << 7;
    int wid  = tid >> 5, lane = tid & 31;
    int wm   = (wid & 3) << 5;
    int wn   = (wid >> 2) << 6;
    int g    = lane >> 2, t = lane & 3;

    float acc[2][8][4];
    #pragma unroll
    for (int mi = 0; mi < 2; mi++)
        #pragma unroll
        for (int ni = 0; ni < 8; ni++)
            #pragma unroll
            for (int c = 0; c < 4; c++) acc[mi][ni][c] = 0.f;

    int a_m = tid >> 3;
    int a_k = (tid & 7) << 3;

    unsigned as_u = (unsigned)__cvta_generic_to_shared(As);
    unsigned bs_u = (unsigned)__cvta_generic_to_shared(Bs);
    int a_off = (wm + (lane & 15)) * HS64 + ((lane >> 4) << 3);
    int b_off = (wn + ((lane >> 4) << 3) + (lane & 7)) * HS64
              + (((lane >> 3) & 1) << 3);

    #define LOAD_A64(si, kb)                                                    \
    {                                                                           \
        __half* as = As + (si) * STG64;                                         \
        _Pragma("unroll")                                                       \
        for (int u = 0; u < 4; u++) {                                           \
            int row = a_m + (u << 5);                                           \
            cp16(as + row * HS64 + a_k,                                         \
                 A + (size_t)(bm + row) * K + (kb) + a_k);                      \
        }                                                                       \
    }
    #define LOAD_B64(si, kb)                                                    \
    {                                                                           \
        __half* bs = Bs + (si) * STG64;                                         \
        _Pragma("unroll")                                                       \
        for (int u = 0; u < 4; u++) {                                           \
            int row = a_m + (u << 5);                                           \
            cp16(bs + row * HS64 + a_k,                                         \
                 Bt + (size_t)(bn + row) * K + (kb) + a_k);                     \
        }                                                                       \
    }
    #define COMMIT() asm volatile("cp.async.commit_group;");

    #define KSTEP(abase, bbase, k0)                                             \
    {                                                                           \
        unsigned af[2][4], bf[8][2];                                            \
        _Pragma("unroll")                                                       \
        for (int mi = 0; mi < 2; mi++)                                          \
            ldm4(af[mi][0], af[mi][1], af[mi][2], af[mi][3],                    \
                 (abase) + (a_off + (mi << 4) * HS64 + (k0)) * 2);              \
        _Pragma("unroll")                                                       \
        for (int p = 0; p < 4; p++)                                             \
            ldm4(bf[2 * p][0], bf[2 * p][1], bf[2 * p + 1][0], bf[2 * p + 1][1],\
                 (bbase) + (b_off + (p << 4) * HS64 + (k0)) * 2);               \
        _Pragma("unroll")                                                       \
        for (int mi = 0; mi < 2; mi++)                                          \
            _Pragma("unroll")                                                   \
            for (int ni = 0; ni < 8; ni++) {                                    \
                asm("mma.sync.aligned.m16n8k16.row.col.f32.f16.f16.f32 "        \
                    "{%0,%1,%2,%3}, {%4,%5,%6,%7}, {%8,%9}, {%0,%1,%2,%3};"     \
                    : "+f"(acc[mi][ni][0]), "+f"(acc[mi][ni][1]),               \
                      "+f"(acc[mi][ni][2]), "+f"(acc[mi][ni][3])                \
                    : "r"(af[mi][0]), "r"(af[mi][1]), "r"(af[mi][2]),           \
                      "r"(af[mi][3]), "r"(bf[ni][0]), "r"(bf[ni][1]));          \
            }                                                                   \
    }

    // one fully-unrolled mainloop iteration with split prefetch
    #define ITER(i, nprefetch, nwait)                                           \
    {                                                                           \
        asm volatile("cp.async.wait_group %0;" :: "n"(nwait));                  \
        __syncthreads();                                                        \
        unsigned abase = as_u + (((i) % 3) * STG64) * 2;                        \
        unsigned bbase = bs_u + (((i) % 3) * STG64) * 2;                        \
        KSTEP(abase, bbase, 0)                                                  \
        if (nprefetch) LOAD_A64(((i) + 2) % 3, ((i) + 2) << 6)                  \
        KSTEP(abase, bbase, 16)                                                 \
        if (nprefetch) { LOAD_B64(((i) + 2) % 3, ((i) + 2) << 6) COMMIT() }     \
        KSTEP(abase, bbase, 32)                                                 \
        KSTEP(abase, bbase, 48)                                                 \
    }

    LOAD_A64(0, 0)  LOAD_B64(0, 0)  COMMIT()
    LOAD_A64(1, 64) LOAD_B64(1, 64) COMMIT()

    if (K == 256) {
        ITER(0, 1, 1)
        ITER(1, 1, 1)
        ITER(2, 0, 1)
        ITER(3, 0, 0)
    } else if (K == 1024) {
        #pragma unroll
        for (int i = 0; i < 14; i++) ITER(i, 1, 1)
        ITER(14, 0, 1)
        ITER(15, 0, 0)
    } else {
        int iters = K >> 6;
        for (int i = 0; i < iters; i++) {
            if (i + 1 < iters) asm volatile("cp.async.wait_group 1;");
            else               asm volatile("cp.async.wait_group 0;");
            __syncthreads();
            unsigned abase = as_u + ((i % 3) * STG64) * 2;
            unsigned bbase = bs_u + ((i % 3) * STG64) * 2;
            KSTEP(abase, bbase, 0)
            if (i + 2 < iters) LOAD_A64((i + 2) % 3, (i + 2) << 6)
            KSTEP(abase, bbase, 16)
            if (i + 2 < iters) { LOAD_B64((i + 2) % 3, (i + 2) << 6) COMMIT() }
            KSTEP(abase, bbase, 32)
            KSTEP(abase, bbase, 48)
        }
    }

    #pragma unroll
    for (int mi = 0; mi < 2; mi++) {
        int row0 = bm + wm + (mi << 4) + g;
        #pragma unroll
        for (int ni = 0; ni < 8; ni++) {
            int col = bn + wn + (ni << 3) + (t << 1);
            float2 bb = *(const float2*)(bias + col);
            float2 u, v;
            u.x = acc[mi][ni][0] + bb.x;
            u.y = acc[mi][ni][1] + bb.y;
            v.x = acc[mi][ni][2] + bb.x;
            v.y = acc[mi][ni][3] + bb.y;
            if (act) {
                u.x = 0.5f * u.x * (1.f + erff(u.x * 0.70710678118654752f));
                u.y = 0.5f * u.y * (1.f + erff(u.y * 0.70710678118654752f));
                v.x = 0.5f * v.x * (1.f + erff(v.x * 0.70710678118654752f));
                v.y = 0.5f * v.y * (1.f + erff(v.y * 0.70710678118654752f));
            }
            size_t o0 = (size_t)row0 * N + col;
            size_t o1 = (size_t)(row0 + 8) * N + col;
            if (out_h16) {
                unsigned* C = (unsigned*)Cv;
                C[o0 >> 1] = pack_h(u.x, u.y);
                C[o1 >> 1] = pack_h(v.x, v.y);
            } else {
                float* C = (float*)Cv;
                if (R) {
                    float2 r0 = *(const float2*)(R + o0);
                    float2 r1 = *(const float2*)(R + o1);
                    u.x += r0.x; u.y += r0.y; v.x += r1.x; v.y += r1.y;
                }
                *(float2*)(C + o0) = u;
                *(float2*)(C + o1) = v;
            }
        }
    }
}

// ---------------------------------------------------------------------------
// fp16 tensor-core window attention (R15): 2 windows per 256-thread CTA.
// ---------------------------------------------------------------------------
__global__ void __launch_bounds__(256)
attn_tc_kernel(const __half* __restrict__ qkv,
               const float* __restrict__ rbt,
               __half* __restrict__ out,
               int masked)
{
    __shared__ __half ks[2][64][40];
    __shared__ __half vs[2][64][40];
    __shared__ __half ps[2][64][72];
    __shared__ float rb[232];

    const float SCALE = 0.17677669529663687f;

    int idx  = blockIdx.x;
    int head = idx & 7;
    int wp   = idx >> 3;
    int tid  = threadIdx.x;
    int warp = tid >> 5, lane = tid & 31;
    int g = lane >> 2, t = lane & 3;

    {
        int sw   = tid >> 7;
        int stid = tid & 127;
        int tok  = stid >> 1;
        int half = (stid & 1) << 4;
        const __half* bq = qkv + (size_t)((wp * 2 + sw) * 64 + tok) * 768 + head * 32 + half;
        uint4 qa = *(const uint4*)(bq);
        uint4 qb = *(const uint4*)(bq + 8);
        *(uint4*)&ps[sw][tok][half]     = qa;
        *(uint4*)&ps[sw][tok][half + 8] = qb;
        uint4 ka = *(const uint4*)(bq + 256);
        uint4 kb = *(const uint4*)(bq + 264);
        *(uint4*)&ks[sw][tok][half]     = ka;
        *(uint4*)&ks[sw][tok][half + 8] = kb;
        uint4 va = *(const uint4*)(bq + 512);
        uint4 vb = *(const uint4*)(bq + 520);
        *(uint4*)&vs[sw][tok][half]     = va;
        *(uint4*)&vs[sw][tok][half + 8] = vb;
    }
    if (tid < 225) rb[tid] = rbt[head * 225 + tid];
    __syncthreads();

    int wloc = warp >> 2;
    int win  = wp * 2 + wloc;
    int wm   = (warp & 3) << 4;
    int i_lo = wm + g, i_hi = i_lo + 8;

    unsigned ks_u = (unsigned)__cvta_generic_to_shared(&ks[wloc][0][0]);
    unsigned vs_u = (unsigned)__cvta_generic_to_shared(&vs[wloc][0][0]);
    unsigned ps_u = (unsigned)__cvta_generic_to_shared(&ps[wloc][0][0]);
    int b_off = (((lane >> 4) << 3) + (lane & 7)) * 40 + (((lane >> 3) & 1) << 3);
    int a_off = (wm + (lane & 15)) * 72 + ((lane >> 4) << 3);

    float sacc[8][4];
    #pragma unroll
    for (int ni = 0; ni < 8; ni++)
        #pragma unroll
        for (int c = 0; c < 4; c++) sacc[ni][c] = 0.f;

    #pragma unroll
    for (int kk = 0; kk < 2; kk++) {
        int k0 = kk << 4;
        unsigned qf[4];
        ldm4(qf[0], qf[1], qf[2], qf[3], ps_u + (a_off + k0) * 2);
        unsigned bf[8][2];
        #pragma unroll
        for (int p = 0; p < 4; p++)
            ldm4(bf[2 * p][0], bf[2 * p][1], bf[2 * p + 1][0], bf[2 * p + 1][1],
                 ks_u + (b_off + (p << 4) * 40 + k0) * 2);
        #pragma unroll
        for (int ni = 0; ni < 8; ni++) {
            asm("mma.sync.aligned.m16n8k16.row.col.f32.f16.f16.f32 "
                "{%0,%1,%2,%3}, {%4,%5,%6,%7}, {%8,%9}, {%0,%1,%2,%3};"
                : "+f"(sacc[ni][0]), "+f"(sacc[ni][1]),
                  "+f"(sacc[ni][2]), "+f"(sacc[ni][3])
                : "r"(qf[0]), "r"(qf[1]), "r"(qf[2]), "r"(qf[3]),
                  "r"(bf[ni][0]), "r"(bf[ni][1]));
        }
    }

    int yi0 = i_lo >> 3, xi0 = i_lo & 7;
    int yi1 = i_hi >> 3, xi1 = i_hi & 7;
    int wi = win & 63;
    int whbase = (wi >> 3) << 3;
    int wwbase = (wi & 7) << 3;
    int reg0 = 0, reg1 = 0;
    if (masked) {
        int h0 = whbase + yi0, w0 = wwbase + xi0;
        int h1 = whbase + yi1, w1 = wwbase + xi1;
        reg0 = ((h0 >= 56) + (h0 >= 60)) * 3 + (w0 >= 56) + (w0 >= 60);
        reg1 = ((h1 >= 56) + (h1 >= 60)) * 3 + (w1 >= 56) + (w1 >= 60);
    }
    #pragma unroll
    for (int ni = 0; ni < 8; ni++) {
        #pragma unroll
        for (int c = 0; c < 2; c++) {
            int j = (ni << 3) + (t << 1) + c;
            int yj = j >> 3, xj = j & 7;
            sacc[ni][c]     = sacc[ni][c]     * SCALE + rb[(yi0 - yj + 7) * 15 + (xi0 - xj + 7)];
            sacc[ni][2 + c] = sacc[ni][2 + c] * SCALE + rb[(yi1 - yj + 7) * 15 + (xi1 - xj + 7)];
            if (masked) {
                int hj = whbase + yj, wj = wwbase + xj;
                int regj = ((hj >= 56) + (hj >= 60)) * 3 + (wj >= 56) + (wj >= 60);
                if (regj != reg0) sacc[ni][c]     -= 100.f;
                if (regj != reg1) sacc[ni][2 + c] -= 100.f;
            }
        }
    }

    float mlo = -1e30f, mhi = -1e30f;
    #pragma unroll
    for (int ni = 0; ni < 8; ni++) {
        mlo = fmaxf(mlo, fmaxf(sacc[ni][0], sacc[ni][1]));
        mhi = fmaxf(mhi, fmaxf(sacc[ni][2], sacc[ni][3]));
    }
    mlo = fmaxf(mlo, __shfl_xor_sync(0xffffffffu, mlo, 1));
    mlo = fmaxf(mlo, __shfl_xor_sync(0xffffffffu, mlo, 2));
    mhi = fmaxf(mhi, __shfl_xor_sync(0xffffffffu, mhi, 1));
    mhi = fmaxf(mhi, __shfl_xor_sync(0xffffffffu, mhi, 2));

    float slo = 0.f, shi = 0.f;
    #pragma unroll
    for (int ni = 0; ni < 8; ni++) {
        sacc[ni][0] = __expf(sacc[ni][0] - mlo);
        sacc[ni][1] = __expf(sacc[ni][1] - mlo);
        sacc[ni][2] = __expf(sacc[ni][2] - mhi);
        sacc[ni][3] = __expf(sacc[ni][3] - mhi);
        slo += sacc[ni][0] + sacc[ni][1];
        shi += sacc[ni][2] + sacc[ni][3];
    }
    slo += __shfl_xor_sync(0xffffffffu, slo, 1);
    slo += __shfl_xor_sync(0xffffffffu, slo, 2);
    shi += __shfl_xor_sync(0xffffffffu, shi, 1);
    shi += __shfl_xor_sync(0xffffffffu, shi, 2);
    float inv_lo = 1.f / slo, inv_hi = 1.f / shi;

    #pragma unroll
    for (int ni = 0; ni < 8; ni++) {
        *(unsigned*)&ps[wloc][i_lo][(ni << 3) + (t << 1)] = pack_h(sacc[ni][0], sacc[ni][1]);
        *(unsigned*)&ps[wloc][i_hi][(ni << 3) + (t << 1)] = pack_h(sacc[ni][2], sacc[ni][3]);
    }
    __syncwarp();

    float oacc[4][4];
    #pragma unroll
    for (int ni = 0; ni < 4; ni++)
        #pragma unroll
        for (int c = 0; c < 4; c++) oacc[ni][c] = 0.f;

    #pragma unroll
    for (int kk = 0; kk < 4; kk++) {
        int k0 = kk << 4;
        unsigned af[4];
        ldm4(af[0], af[1], af[2], af[3], ps_u + (a_off + k0) * 2);
        #pragma unroll
        for (int ni = 0; ni < 4; ni++) {
            unsigned b0, b1;
            ldm2t(b0, b1, vs_u + ((k0 + (lane & 15)) * 40 + (ni << 3)) * 2);
            asm("mma.sync.aligned.m16n8k16.row.col.f32.f16.f16.f32 "
                "{%0,%1,%2,%3}, {%4,%5,%6,%7}, {%8,%9}, {%0,%1,%2,%3};"
                : "+f"(oacc[ni][0]), "+f"(oacc[ni][1]),
                  "+f"(oacc[ni][2]), "+f"(oacc[ni][3])
                : "r"(af[0]), "r"(af[1]), "r"(af[2]), "r"(af[3]),
                  "r"(b0), "r"(b1));
        }
    }

    __half* olo = out + (size_t)(win * 64 + i_lo) * 256 + head * 32;
    __half* ohi = out + (size_t)(win * 64 + i_hi) * 256 + head * 32;
    #pragma unroll
    for (int ni = 0; ni < 4; ni++) {
        int col = (ni << 3) + (t << 1);
        *(unsigned*)(olo + col) = pack_h(oacc[ni][0] * inv_lo, oacc[ni][1] * inv_lo);
        *(unsigned*)(ohi + col) = pack_h(oacc[ni][2] * inv_hi, oacc[ni][3] * inv_hi);
    }
}

// ---------------------------------------------------------------------------
extern "C" void kernel_launch(void* const* d_in, const int* in_sizes, int n_in,
                              void* d_out, int out_size)
{
    (void)in_sizes; (void)n_in; (void)out_size;

    __half *xw, *qkv, *attnb, *h2, *mlp, *wt, *proj;
    float* rbt;
    cudaGetSymbolAddress((void**)&xw,    g_xw);
    cudaGetSymbolAddress((void**)&qkv,   g_qkv);
    cudaGetSymbolAddress((void**)&attnb, g_attn);
    cudaGetSymbolAddress((void**)&h2,    g_h2);
    cudaGetSymbolAddress((void**)&mlp,   g_mlp);
    cudaGetSymbolAddress((void**)&proj,  g_proj);
    cudaGetSymbolAddress((void**)&wt,    g_wt);
    cudaGetSymbolAddress((void**)&rbt,   g_rbt);

    cudaFuncSetAttribute(h_gemm_kernel,
                         cudaFuncAttributeMaxDynamicSharedMemorySize, GEMM_SMEM64);

    const float* x_in = (const float*)d_in[0];
    float* x = (float*)d_out;

    WtArgs wa;
    for (int blk = 0; blk < 2; blk++) {
        int base = 1 + 13 * blk;
        wa.w[blk * 4 + 0] = (const float*)d_in[base + 2];
        wa.w[blk * 4 + 1] = (const float*)d_in[base + 5];
        wa.w[blk * 4 + 2] = (const float*)d_in[base + 9];
        wa.w[blk * 4 + 3] = (const float*)d_in[base + 11];
        __half* wb = wt + blk * 786432;
        wa.o[blk * 4 + 0] = wb;
        wa.o[blk * 4 + 1] = wb + 196608;
        wa.o[blk * 4 + 2] = wb + 262144;
        wa.o[blk * 4 + 3] = wb + 524288;
    }
    wt_all_kernel<<<1536, dim3(32, 8)>>>(wa);
    rpb_gather_kernel<<<16, 256>>>((const float*)d_in[1 + 4],
                                   (const float*)d_in[1 + 13 + 4], rbt);

    for (int blk = 0; blk < 2; blk++) {
        int base = 1 + 13 * blk;
        const float* n1g  = (const float*)d_in[base + 0];
        const float* n1b  = (const float*)d_in[base + 1];
        const float* qkvb = (const float*)d_in[base + 3];
        const float* pb   = (const float*)d_in[base + 6];
        const float* n2g  = (const float*)d_in[base + 7];
        const float* n2b  = (const float*)d_in[base + 8];
        const float* f1b  = (const float*)d_in[base + 10];
        const float* f2b  = (const float*)d_in[base + 12];

        __half* wb   = wt + blk * 786432;
        __half* qkvt = wb;
        __half* pwt  = wb + 196608;
        __half* f1t  = wb + 262144;
        __half* f2t  = wb + 524288;

        int shift  = blk ? 4 : 0;
        int masked = blk;
        const float* x_cur = blk ? x : x_in;

        ln_kernel<<<8192, 256>>>(x_cur, n1g, n1b, xw, shift);
        h_gemm_kernel<<<dim3(6, 512), 256, GEMM_SMEM64>>>(
            xw, qkvt, qkvb, nullptr, qkv, 768, 256, 0, 1);
        attn_tc_kernel<<<4096, 256>>>(qkv, rbt + blk * 8 * 225, attnb, masked);
        h_gemm_kernel<<<dim3(2, 512), 256, GEMM_SMEM64>>>(
            attnb, pwt, pb, nullptr, proj, 256, 256, 0, 1);
        rev_ln_kernel<<<8192, 256>>>(proj, x_cur, x, n2g, n2b, h2, shift);
        h_gemm_kernel<<<dim3(8, 512), 256, GEMM_SMEM64>>>(
            h2, f1t, f1b, nullptr, mlp, 1024, 256, 1, 1);
        h_gemm_kernel<<<dim3(2, 512), 256, GEMM_SMEM64>>>(
            mlp, f2t, f2b, x, x, 256, 1024, 0, 0);
    }
}

// round 17
// speedup vs baseline: 1.5206x; 1.0256x over previous
#include <cuda_runtime.h>
#include <cuda_fp16.h>
#include <math.h>

// ---------------------------------------------------------------------------
// Swin: B=16, H=W=64, DIM=256, HEADS=8, HD=32, WS=8, N=64, NW=64, MLP_H=1024
// fp16 datapath + fp16 intermediate residual stream; fp32 accumulate;
// final output fp32.
// ---------------------------------------------------------------------------

#define NTOK 65536

static __device__ __half g_xw  [NTOK * 256];
static __device__ __half g_qkv [NTOK * 768];
static __device__ __half g_attn[NTOK * 256];
static __device__ __half g_h2  [NTOK * 256];
static __device__ __half g_mlp [NTOK * 1024];
static __device__ __half g_proj[NTOK * 256];
static __device__ __half g_x16 [NTOK * 256];   // fp16 residual stream
static __device__ __half g_wt  [2 * 786432];
static __device__ float  g_rbt [2 * 8 * 225];

__device__ __forceinline__ unsigned pack_h(float x, float y) {
    __half2 h = __floats2half2_rn(x, y);
    return *(unsigned*)&h;
}

// ---------------------------------------------------------------------------
// Merged weight convert+transpose for BOTH blocks: W[K][N] fp32 -> Wt[N][K] fp16
// ---------------------------------------------------------------------------
struct WtArgs {
    const float* w[8];
    __half*      o[8];
};

__global__ void wt_all_kernel(WtArgs args)
{
    __shared__ float tile[32][33];
    int b = blockIdx.x;
    int blk = b >= 768;
    b -= blk * 768;
    const float* W; __half* Wt; int K, N, nb, sel;
    if (b < 192)      { sel = 0; K = 256;  N = 768;  nb = 24; }
    else if (b < 256) { b -= 192; sel = 1; K = 256;  N = 256;  nb = 8; }
    else if (b < 512) { b -= 256; sel = 2; K = 256;  N = 1024; nb = 32; }
    else              { b -= 512; sel = 3; K = 1024; N = 256;  nb = 8; }
    W  = args.w[blk * 4 + sel];
    Wt = args.o[blk * 4 + sel];
    int n0 = (b % nb) << 5, k0 = (b / nb) << 5;
    int tx = threadIdx.x, ty = threadIdx.y;
    #pragma unroll
    for (int i = 0; i < 4; i++)
        tile[ty + i * 8][tx] = W[(size_t)(k0 + ty + i * 8) * N + n0 + tx];
    __syncthreads();
    #pragma unroll
    for (int i = 0; i < 4; i++)
        Wt[(size_t)(n0 + ty + i * 8) * K + k0 + tx] =
            __float2half_rn(tile[tx][ty + i * 8]);
}

// ---------------------------------------------------------------------------
// rpb gather: rpb[225][8] -> rbt[blk][head][225]
// ---------------------------------------------------------------------------
__global__ void rpb_gather_kernel(const float* __restrict__ rpb0,
                                  const float* __restrict__ rpb1,
                                  float* __restrict__ rbt)
{
    int blk  = blockIdx.x >> 3;
    int head = blockIdx.x & 7;
    const float* rpb = blk ? rpb1 : rpb0;
    int tid = threadIdx.x;
    if (tid < 225)
        rbt[(blk * 8 + head) * 225 + tid] = rpb[tid * 8 + head];
}

// ---------------------------------------------------------------------------
// LayerNorm (+shift + window partition) -> fp16 out. One warp/row.
// Source: fp32 (in16=0) or fp16 (in16=1); identical per-lane channel layout.
// ---------------------------------------------------------------------------
__global__ void ln_kernel(const float* __restrict__ xf,
                          const __half* __restrict__ xh,
                          const float* __restrict__ gamma,
                          const float* __restrict__ beta,
                          __half* __restrict__ out,
                          int shift, int in16)
{
    int gw   = (blockIdx.x * blockDim.x + threadIdx.x) >> 5;
    int lane = threadIdx.x & 31;
    if (gw >= NTOK) return;

    int win = gw >> 6, n = gw & 63;
    int b  = win >> 6, wi = win & 63;
    int h  = (((wi >> 3) << 3) + (n >> 3) + shift) & 63;
    int w  = (((wi & 7)  << 3) + (n & 7)  + shift) & 63;
    int src = (b << 12) + (h << 6) + w;

    float4 v0, v1;
    if (in16) {
        const uint2* p = (const uint2*)(xh + (size_t)src * 256);
        uint2 a = p[lane];          // halves 4l..4l+3
        uint2 c = p[lane + 32];     // halves 128+4l..
        float2 f0 = __half22float2(*(__half2*)&a.x);
        float2 f1 = __half22float2(*(__half2*)&a.y);
        float2 f2 = __half22float2(*(__half2*)&c.x);
        float2 f3 = __half22float2(*(__half2*)&c.y);
        v0 = make_float4(f0.x, f0.y, f1.x, f1.y);
        v1 = make_float4(f2.x, f2.y, f3.x, f3.y);
    } else {
        const float4* xr = (const float4*)xf + (size_t)src * 64;
        v0 = xr[lane];
        v1 = xr[lane + 32];
    }

    float s = v0.x + v0.y + v0.z + v0.w + v1.x + v1.y + v1.z + v1.w;
    #pragma unroll
    for (int o = 16; o; o >>= 1) s += __shfl_xor_sync(0xffffffffu, s, o);
    float mean = s * (1.0f / 256.0f);

    float a, ss = 0.f;
    a = v0.x - mean; ss += a * a;  a = v0.y - mean; ss += a * a;
    a = v0.z - mean; ss += a * a;  a = v0.w - mean; ss += a * a;
    a = v1.x - mean; ss += a * a;  a = v1.y - mean; ss += a * a;
    a = v1.z - mean; ss += a * a;  a = v1.w - mean; ss += a * a;
    #pragma unroll
    for (int o = 16; o; o >>= 1) ss += __shfl_xor_sync(0xffffffffu, ss, o);
    float rstd = rsqrtf(ss * (1.0f / 256.0f) + 1e-5f);

    const float4* g4 = (const float4*)gamma;
    const float4* b4 = (const float4*)beta;
    float4 g0 = g4[lane], g1 = g4[lane + 32];
    float4 c0 = b4[lane], c1 = b4[lane + 32];

    unsigned* o32 = (unsigned*)(out + (size_t)gw * 256);
    uint2 r0, r1;
    r0.x = pack_h((v0.x - mean) * rstd * g0.x + c0.x,
                  (v0.y - mean) * rstd * g0.y + c0.y);
    r0.y = pack_h((v0.z - mean) * rstd * g0.z + c0.z,
                  (v0.w - mean) * rstd * g0.w + c0.w);
    r1.x = pack_h((v1.x - mean) * rstd * g1.x + c1.x,
                  (v1.y - mean) * rstd * g1.y + c1.y);
    r1.y = pack_h((v1.z - mean) * rstd * g1.z + c1.z,
                  (v1.w - mean) * rstd * g1.w + c1.w);
    *(uint2*)(o32 + lane * 2)      = r0;
    *(uint2*)(o32 + 64 + lane * 2) = r1;
}

// ---------------------------------------------------------------------------
// Fused window-reverse + un-shift + residual + LayerNorm2.
// x_dst (fp16) = x_src (fp32/fp16) + rev(proj);  h2 = LN(x_dst).
// ---------------------------------------------------------------------------
__global__ void rev_ln_kernel(const __half* __restrict__ proj,
                              const float* __restrict__ xf_src,
                              const __half* __restrict__ xh_src,
                              __half* __restrict__ x_dst,
                              const float* __restrict__ gamma,
                              const float* __restrict__ beta,
                              __half* __restrict__ h2,
                              int shift, int in16)
{
    int gw   = (blockIdx.x * blockDim.x + threadIdx.x) >> 5;
    int lane = threadIdx.x & 31;
    if (gw >= NTOK) return;

    int b = gw >> 12, h = (gw >> 6) & 63, w = gw & 63;
    int hh = (h - shift) & 63, ww = (w - shift) & 63;
    int row = ((b << 6) + ((hh >> 3) << 3) + (ww >> 3)) * 64
            + ((hh & 7) << 3) + (ww & 7);

    float4 v0, v1;
    if (in16) {
        const uint2* p = (const uint2*)(xh_src + (size_t)gw * 256);
        uint2 a = p[lane];
        uint2 c = p[lane + 32];
        float2 f0 = __half22float2(*(__half2*)&a.x);
        float2 f1 = __half22float2(*(__half2*)&a.y);
        float2 f2 = __half22float2(*(__half2*)&c.x);
        float2 f3 = __half22float2(*(__half2*)&c.y);
        v0 = make_float4(f0.x, f0.y, f1.x, f1.y);
        v1 = make_float4(f2.x, f2.y, f3.x, f3.y);
    } else {
        const float4* xr = (const float4*)xf_src + (size_t)gw * 64;
        v0 = xr[lane];
        v1 = xr[lane + 32];
    }

    const __half2* pr = (const __half2*)(proj + (size_t)row * 256);
    __half2 pa = pr[lane * 2],      pb = pr[lane * 2 + 1];
    __half2 pc = pr[64 + lane * 2], pd = pr[64 + lane * 2 + 1];
    float2 fa = __half22float2(pa), fb = __half22float2(pb);
    float2 fc = __half22float2(pc), fd = __half22float2(pd);
    v0.x += fa.x; v0.y += fa.y; v0.z += fb.x; v0.w += fb.y;
    v1.x += fc.x; v1.y += fc.y; v1.z += fd.x; v1.w += fd.y;

    // write x_dst in fp16 (same per-lane channel layout)
    uint2* xo = (uint2*)(x_dst + (size_t)gw * 256);
    uint2 w0, w1;
    w0.x = pack_h(v0.x, v0.y);  w0.y = pack_h(v0.z, v0.w);
    w1.x = pack_h(v1.x, v1.y);  w1.y = pack_h(v1.z, v1.w);
    xo[lane]      = w0;
    xo[lane + 32] = w1;

    float s = v0.x + v0.y + v0.z + v0.w + v1.x + v1.y + v1.z + v1.w;
    #pragma unroll
    for (int o = 16; o; o >>= 1) s += __shfl_xor_sync(0xffffffffu, s, o);
    float mean = s * (1.0f / 256.0f);

    float a, ss = 0.f;
    a = v0.x - mean; ss += a * a;  a = v0.y - mean; ss += a * a;
    a = v0.z - mean; ss += a * a;  a = v0.w - mean; ss += a * a;
    a = v1.x - mean; ss += a * a;  a = v1.y - mean; ss += a * a;
    a = v1.z - mean; ss += a * a;  a = v1.w - mean; ss += a * a;
    #pragma unroll
    for (int o = 16; o; o >>= 1) ss += __shfl_xor_sync(0xffffffffu, ss, o);
    float rstd = rsqrtf(ss * (1.0f / 256.0f) + 1e-5f);

    const float4* g4 = (const float4*)gamma;
    const float4* b4 = (const float4*)beta;
    float4 g0 = g4[lane], g1 = g4[lane + 32];
    float4 c0 = b4[lane], c1 = b4[lane + 32];

    unsigned* o32 = (unsigned*)(h2 + (size_t)gw * 256);
    uint2 r0, r1;
    r0.x = pack_h((v0.x - mean) * rstd * g0.x + c0.x,
                  (v0.y - mean) * rstd * g0.y + c0.y);
    r0.y = pack_h((v0.z - mean) * rstd * g0.z + c0.z,
                  (v0.w - mean) * rstd * g0.w + c0.w);
    r1.x = pack_h((v1.x - mean) * rstd * g1.x + c1.x,
                  (v1.y - mean) * rstd * g1.y + c1.y);
    r1.y = pack_h((v1.z - mean) * rstd * g1.z + c1.z,
                  (v1.w - mean) * rstd * g1.w + c1.w);
    *(uint2*)(o32 + lane * 2)      = r0;
    *(uint2*)(o32 + 64 + lane * 2) = r1;
}

// ---------------------------------------------------------------------------
// fp16 tensor-core GEMM, BK=64 (R16 winner): unrolled K=256/K=1024 paths,
// split A/B prefetch. Residual pointer is fp16.
// ---------------------------------------------------------------------------
#define HS64 72
#define STG64 (128 * HS64)
#define GEMM_SMEM64 (3 * 2 * STG64 * 2)    // 110592 bytes

__device__ __forceinline__ void cp16(void* s, const void* g) {
    unsigned sa = (unsigned)__cvta_generic_to_shared(s);
    asm volatile("cp.async.cg.shared.global [%0], [%1], 16;" :: "r"(sa), "l"(g));
}

__device__ __forceinline__ void ldm4(unsigned& r0, unsigned& r1,
                                     unsigned& r2, unsigned& r3, unsigned addr) {
    asm volatile("ldmatrix.sync.aligned.m8n8.x4.shared.b16 {%0,%1,%2,%3}, [%4];"
                 : "=r"(r0), "=r"(r1), "=r"(r2), "=r"(r3) : "r"(addr));
}

__device__ __forceinline__ void ldm2t(unsigned& r0, unsigned& r1, unsigned addr) {
    asm volatile("ldmatrix.sync.aligned.m8n8.x2.trans.shared.b16 {%0,%1}, [%2];"
                 : "=r"(r0), "=r"(r1) : "r"(addr));
}

__global__ void __launch_bounds__(256, 2)
h_gemm_kernel(const __half* __restrict__ A,
              const __half* __restrict__ Bt,
              const float* __restrict__ bias,
              const __half* __restrict__ Rh,
              void* __restrict__ Cv,
              int N, int K, int act, int out_h16)
{
    extern __shared__ __half smem[];
    __half* As = smem;
    __half* Bs = smem + 3 * STG64;

    int tid  = threadIdx.x;
    int bm   = blockIdx.y << 7;
    int bn   = blockIdx.x << 7;
    int wid  = tid >> 5, lane = tid & 31;
    int wm   = (wid & 3) << 5;
    int wn   = (wid >> 2) << 6;
    int g    = lane >> 2, t = lane & 3;

    float acc[2][8][4];
    #pragma unroll
    for (int mi = 0; mi < 2; mi++)
        #pragma unroll
        for (int ni = 0; ni < 8; ni++)
            #pragma unroll
            for (int c = 0; c < 4; c++) acc[mi][ni][c] = 0.f;

    int a_m = tid >> 3;
    int a_k = (tid & 7) << 3;

    unsigned as_u = (unsigned)__cvta_generic_to_shared(As);
    unsigned bs_u = (unsigned)__cvta_generic_to_shared(Bs);
    int a_off = (wm + (lane & 15)) * HS64 + ((lane >> 4) << 3);
    int b_off = (wn + ((lane >> 4) << 3) + (lane & 7)) * HS64
              + (((lane >> 3) & 1) << 3);

    #define LOAD_A64(si, kb)                                                    \
    {                                                                           \
        __half* as = As + (si) * STG64;                                         \
        _Pragma("unroll")                                                       \
        for (int u = 0; u < 4; u++) {                                           \
            int row = a_m + (u << 5);                                           \
            cp16(as + row * HS64 + a_k,                                         \
                 A + (size_t)(bm + row) * K + (kb) + a_k);                      \
        }                                                                       \
    }
    #define LOAD_B64(si, kb)                                                    \
    {                                                                           \
        __half* bs = Bs + (si) * STG64;                                         \
        _Pragma("unroll")                                                       \
        for (int u = 0; u < 4; u++) {                                           \
            int row = a_m + (u << 5);                                           \
            cp16(bs + row * HS64 + a_k,                                         \
                 Bt + (size_t)(bn + row) * K + (kb) + a_k);                     \
        }                                                                       \
    }
    #define COMMIT() asm volatile("cp.async.commit_group;");

    #define KSTEP(abase, bbase, k0)                                             \
    {                                                                           \
        unsigned af[2][4], bf[8][2];                                            \
        _Pragma("unroll")                                                       \
        for (int mi = 0; mi < 2; mi++)                                          \
            ldm4(af[mi][0], af[mi][1], af[mi][2], af[mi][3],                    \
                 (abase) + (a_off + (mi << 4) * HS64 + (k0)) * 2);              \
        _Pragma("unroll")                                                       \
        for (int p = 0; p < 4; p++)                                             \
            ldm4(bf[2 * p][0], bf[2 * p][1], bf[2 * p + 1][0], bf[2 * p + 1][1],\
                 (bbase) + (b_off + (p << 4) * HS64 + (k0)) * 2);               \
        _Pragma("unroll")                                                       \
        for (int mi = 0; mi < 2; mi++)                                          \
            _Pragma("unroll")                                                   \
            for (int ni = 0; ni < 8; ni++) {                                    \
                asm("mma.sync.aligned.m16n8k16.row.col.f32.f16.f16.f32 "        \
                    "{%0,%1,%2,%3}, {%4,%5,%6,%7}, {%8,%9}, {%0,%1,%2,%3};"     \
                    : "+f"(acc[mi][ni][0]), "+f"(acc[mi][ni][1]),               \
                      "+f"(acc[mi][ni][2]), "+f"(acc[mi][ni][3])                \
                    : "r"(af[mi][0]), "r"(af[mi][1]), "r"(af[mi][2]),           \
                      "r"(af[mi][3]), "r"(bf[ni][0]), "r"(bf[ni][1]));          \
            }                                                                   \
    }

    #define ITER(i, nprefetch, nwait)                                           \
    {                                                                           \
        asm volatile("cp.async.wait_group %0;" :: "n"(nwait));                  \
        __syncthreads();                                                        \
        unsigned abase = as_u + (((i) % 3) * STG64) * 2;                        \
        unsigned bbase = bs_u + (((i) % 3) * STG64) * 2;                        \
        KSTEP(abase, bbase, 0)                                                  \
        if (nprefetch) LOAD_A64(((i) + 2) % 3, ((i) + 2) << 6)                  \
        KSTEP(abase, bbase, 16)                                                 \
        if (nprefetch) { LOAD_B64(((i) + 2) % 3, ((i) + 2) << 6) COMMIT() }     \
        KSTEP(abase, bbase, 32)                                                 \
        KSTEP(abase, bbase, 48)                                                 \
    }

    LOAD_A64(0, 0)  LOAD_B64(0, 0)  COMMIT()
    LOAD_A64(1, 64) LOAD_B64(1, 64) COMMIT()

    if (K == 256) {
        ITER(0, 1, 1)
        ITER(1, 1, 1)
        ITER(2, 0, 1)
        ITER(3, 0, 0)
    } else if (K == 1024) {
        #pragma unroll
        for (int i = 0; i < 14; i++) ITER(i, 1, 1)
        ITER(14, 0, 1)
        ITER(15, 0, 0)
    } else {
        int iters = K >> 6;
        for (int i = 0; i < iters; i++) {
            if (i + 1 < iters) asm volatile("cp.async.wait_group 1;");
            else               asm volatile("cp.async.wait_group 0;");
            __syncthreads();
            unsigned abase = as_u + ((i % 3) * STG64) * 2;
            unsigned bbase = bs_u + ((i % 3) * STG64) * 2;
            KSTEP(abase, bbase, 0)
            if (i + 2 < iters) LOAD_A64((i + 2) % 3, (i + 2) << 6)
            KSTEP(abase, bbase, 16)
            if (i + 2 < iters) { LOAD_B64((i + 2) % 3, (i + 2) << 6) COMMIT() }
            KSTEP(abase, bbase, 32)
            KSTEP(abase, bbase, 48)
        }
    }

    #pragma unroll
    for (int mi = 0; mi < 2; mi++) {
        int row0 = bm + wm + (mi << 4) + g;
        #pragma unroll
        for (int ni = 0; ni < 8; ni++) {
            int col = bn + wn + (ni << 3) + (t << 1);
            float2 bb = *(const float2*)(bias + col);
            float2 u, v;
            u.x = acc[mi][ni][0] + bb.x;
            u.y = acc[mi][ni][1] + bb.y;
            v.x = acc[mi][ni][2] + bb.x;
            v.y = acc[mi][ni][3] + bb.y;
            if (act) {
                u.x = 0.5f * u.x * (1.f + erff(u.x * 0.70710678118654752f));
                u.y = 0.5f * u.y * (1.f + erff(u.y * 0.70710678118654752f));
                v.x = 0.5f * v.x * (1.f + erff(v.x * 0.70710678118654752f));
                v.y = 0.5f * v.y * (1.f + erff(v.y * 0.70710678118654752f));
            }
            size_t o0 = (size_t)row0 * N + col;
            size_t o1 = (size_t)(row0 + 8) * N + col;
            if (Rh) {
                float2 r0 = __half22float2(*(const __half2*)(Rh + o0));
                float2 r1 = __half22float2(*(const __half2*)(Rh + o1));
                u.x += r0.x; u.y += r0.y; v.x += r1.x; v.y += r1.y;
            }
            if (out_h16) {
                unsigned* C = (unsigned*)Cv;
                C[o0 >> 1] = pack_h(u.x, u.y);
                C[o1 >> 1] = pack_h(v.x, v.y);
            } else {
                float* C = (float*)Cv;
                *(float2*)(C + o0) = u;
                *(float2*)(C + o1) = v;
            }
        }
    }
}

// ---------------------------------------------------------------------------
// fp16 tensor-core window attention (R16): 2 windows per 256-thread CTA.
// ---------------------------------------------------------------------------
__global__ void __launch_bounds__(256)
attn_tc_kernel(const __half* __restrict__ qkv,
               const float* __restrict__ rbt,
               __half* __restrict__ out,
               int masked)
{
    __shared__ __half ks[2][64][40];
    __shared__ __half vs[2][64][40];
    __shared__ __half ps[2][64][72];
    __shared__ float rb[232];

    const float SCALE = 0.17677669529663687f;

    int idx  = blockIdx.x;
    int head = idx & 7;
    int wp   = idx >> 3;
    int tid  = threadIdx.x;
    int warp = tid >> 5, lane = tid & 31;
    int g = lane >> 2, t = lane & 3;

    {
        int sw   = tid >> 7;
        int stid = tid & 127;
        int tok  = stid >> 1;
        int half = (stid & 1) << 4;
        const __half* bq = qkv + (size_t)((wp * 2 + sw) * 64 + tok) * 768 + head * 32 + half;
        uint4 qa = *(const uint4*)(bq);
        uint4 qb = *(const uint4*)(bq + 8);
        *(uint4*)&ps[sw][tok][half]     = qa;
        *(uint4*)&ps[sw][tok][half + 8] = qb;
        uint4 ka = *(const uint4*)(bq + 256);
        uint4 kb = *(const uint4*)(bq + 264);
        *(uint4*)&ks[sw][tok][half]     = ka;
        *(uint4*)&ks[sw][tok][half + 8] = kb;
        uint4 va = *(const uint4*)(bq + 512);
        uint4 vb = *(const uint4*)(bq + 520);
        *(uint4*)&vs[sw][tok][half]     = va;
        *(uint4*)&vs[sw][tok][half + 8] = vb;
    }
    if (tid < 225) rb[tid] = rbt[head * 225 + tid];
    __syncthreads();

    int wloc = warp >> 2;
    int win  = wp * 2 + wloc;
    int wm   = (warp & 3) << 4;
    int i_lo = wm + g, i_hi = i_lo + 8;

    unsigned ks_u = (unsigned)__cvta_generic_to_shared(&ks[wloc][0][0]);
    unsigned vs_u = (unsigned)__cvta_generic_to_shared(&vs[wloc][0][0]);
    unsigned ps_u = (unsigned)__cvta_generic_to_shared(&ps[wloc][0][0]);
    int b_off = (((lane >> 4) << 3) + (lane & 7)) * 40 + (((lane >> 3) & 1) << 3);
    int a_off = (wm + (lane & 15)) * 72 + ((lane >> 4) << 3);

    float sacc[8][4];
    #pragma unroll
    for (int ni = 0; ni < 8; ni++)
        #pragma unroll
        for (int c = 0; c < 4; c++) sacc[ni][c] = 0.f;

    #pragma unroll
    for (int kk = 0; kk < 2; kk++) {
        int k0 = kk << 4;
        unsigned qf[4];
        ldm4(qf[0], qf[1], qf[2], qf[3], ps_u + (a_off + k0) * 2);
        unsigned bf[8][2];
        #pragma unroll
        for (int p = 0; p < 4; p++)
            ldm4(bf[2 * p][0], bf[2 * p][1], bf[2 * p + 1][0], bf[2 * p + 1][1],
                 ks_u + (b_off + (p << 4) * 40 + k0) * 2);
        #pragma unroll
        for (int ni = 0; ni < 8; ni++) {
            asm("mma.sync.aligned.m16n8k16.row.col.f32.f16.f16.f32 "
                "{%0,%1,%2,%3}, {%4,%5,%6,%7}, {%8,%9}, {%0,%1,%2,%3};"
                : "+f"(sacc[ni][0]), "+f"(sacc[ni][1]),
                  "+f"(sacc[ni][2]), "+f"(sacc[ni][3])
                : "r"(qf[0]), "r"(qf[1]), "r"(qf[2]), "r"(qf[3]),
                  "r"(bf[ni][0]), "r"(bf[ni][1]));
        }
    }

    int yi0 = i_lo >> 3, xi0 = i_lo & 7;
    int yi1 = i_hi >> 3, xi1 = i_hi & 7;
    int wi = win & 63;
    int whbase = (wi >> 3) << 3;
    int wwbase = (wi & 7) << 3;
    int reg0 = 0, reg1 = 0;
    if (masked) {
        int h0 = whbase + yi0, w0 = wwbase + xi0;
        int h1 = whbase + yi1, w1 = wwbase + xi1;
        reg0 = ((h0 >= 56) + (h0 >= 60)) * 3 + (w0 >= 56) + (w0 >= 60);
        reg1 = ((h1 >= 56) + (h1 >= 60)) * 3 + (w1 >= 56) + (w1 >= 60);
    }
    #pragma unroll
    for (int ni = 0; ni < 8; ni++) {
        #pragma unroll
        for (int c = 0; c < 2; c++) {
            int j = (ni << 3) + (t << 1) + c;
            int yj = j >> 3, xj = j & 7;
            sacc[ni][c]     = sacc[ni][c]     * SCALE + rb[(yi0 - yj + 7) * 15 + (xi0 - xj + 7)];
            sacc[ni][2 + c] = sacc[ni][2 + c] * SCALE + rb[(yi1 - yj + 7) * 15 + (xi1 - xj + 7)];
            if (masked) {
                int hj = whbase + yj, wj = wwbase + xj;
                int regj = ((hj >= 56) + (hj >= 60)) * 3 + (wj >= 56) + (wj >= 60);
                if (regj != reg0) sacc[ni][c]     -= 100.f;
                if (regj != reg1) sacc[ni][2 + c] -= 100.f;
            }
        }
    }

    float mlo = -1e30f, mhi = -1e30f;
    #pragma unroll
    for (int ni = 0; ni < 8; ni++) {
        mlo = fmaxf(mlo, fmaxf(sacc[ni][0], sacc[ni][1]));
        mhi = fmaxf(mhi, fmaxf(sacc[ni][2], sacc[ni][3]));
    }
    mlo = fmaxf(mlo, __shfl_xor_sync(0xffffffffu, mlo, 1));
    mlo = fmaxf(mlo, __shfl_xor_sync(0xffffffffu, mlo, 2));
    mhi = fmaxf(mhi, __shfl_xor_sync(0xffffffffu, mhi, 1));
    mhi = fmaxf(mhi, __shfl_xor_sync(0xffffffffu, mhi, 2));

    float slo = 0.f, shi = 0.f;
    #pragma unroll
    for (int ni = 0; ni < 8; ni++) {
        sacc[ni][0] = __expf(sacc[ni][0] - mlo);
        sacc[ni][1] = __expf(sacc[ni][1] - mlo);
        sacc[ni][2] = __expf(sacc[ni][2] - mhi);
        sacc[ni][3] = __expf(sacc[ni][3] - mhi);
        slo += sacc[ni][0] + sacc[ni][1];
        shi += sacc[ni][2] + sacc[ni][3];
    }
    slo += __shfl_xor_sync(0xffffffffu, slo, 1);
    slo += __shfl_xor_sync(0xffffffffu, slo, 2);
    shi += __shfl_xor_sync(0xffffffffu, shi, 1);
    shi += __shfl_xor_sync(0xffffffffu, shi, 2);
    float inv_lo = 1.f / slo, inv_hi = 1.f / shi;

    #pragma unroll
    for (int ni = 0; ni < 8; ni++) {
        *(unsigned*)&ps[wloc][i_lo][(ni << 3) + (t << 1)] = pack_h(sacc[ni][0], sacc[ni][1]);
        *(unsigned*)&ps[wloc][i_hi][(ni << 3) + (t << 1)] = pack_h(sacc[ni][2], sacc[ni][3]);
    }
    __syncwarp();

    float oacc[4][4];
    #pragma unroll
    for (int ni = 0; ni < 4; ni++)
        #pragma unroll
        for (int c = 0; c < 4; c++) oacc[ni][c] = 0.f;

    #pragma unroll
    for (int kk = 0; kk < 4; kk++) {
        int k0 = kk << 4;
        unsigned af[4];
        ldm4(af[0], af[1], af[2], af[3], ps_u + (a_off + k0) * 2);
        #pragma unroll
        for (int ni = 0; ni < 4; ni++) {
            unsigned b0, b1;
            ldm2t(b0, b1, vs_u + ((k0 + (lane & 15)) * 40 + (ni << 3)) * 2);
            asm("mma.sync.aligned.m16n8k16.row.col.f32.f16.f16.f32 "
                "{%0,%1,%2,%3}, {%4,%5,%6,%7}, {%8,%9}, {%0,%1,%2,%3};"
                : "+f"(oacc[ni][0]), "+f"(oacc[ni][1]),
                  "+f"(oacc[ni][2]), "+f"(oacc[ni][3])
                : "r"(af[0]), "r"(af[1]), "r"(af[2]), "r"(af[3]),
                  "r"(b0), "r"(b1));
        }
    }

    __half* olo = out + (size_t)(win * 64 + i_lo) * 256 + head * 32;
    __half* ohi = out + (size_t)(win * 64 + i_hi) * 256 + head * 32;
    #pragma unroll
    for (int ni = 0; ni < 4; ni++) {
        int col = (ni << 3) + (t << 1);
        *(unsigned*)(olo + col) = pack_h(oacc[ni][0] * inv_lo, oacc[ni][1] * inv_lo);
        *(unsigned*)(ohi + col) = pack_h(oacc[ni][2] * inv_hi, oacc[ni][3] * inv_hi);
    }
}

// ---------------------------------------------------------------------------
extern "C" void kernel_launch(void* const* d_in, const int* in_sizes, int n_in,
                              void* d_out, int out_size)
{
    (void)in_sizes; (void)n_in; (void)out_size;

    __half *xw, *qkv, *attnb, *h2, *mlp, *wt, *proj, *x16;
    float* rbt;
    cudaGetSymbolAddress((void**)&xw,    g_xw);
    cudaGetSymbolAddress((void**)&qkv,   g_qkv);
    cudaGetSymbolAddress((void**)&attnb, g_attn);
    cudaGetSymbolAddress((void**)&h2,    g_h2);
    cudaGetSymbolAddress((void**)&mlp,   g_mlp);
    cudaGetSymbolAddress((void**)&proj,  g_proj);
    cudaGetSymbolAddress((void**)&x16,   g_x16);
    cudaGetSymbolAddress((void**)&wt,    g_wt);
    cudaGetSymbolAddress((void**)&rbt,   g_rbt);

    cudaFuncSetAttribute(h_gemm_kernel,
                         cudaFuncAttributeMaxDynamicSharedMemorySize, GEMM_SMEM64);

    const float* x_in = (const float*)d_in[0];
    float* x_out = (float*)d_out;

    WtArgs wa;
    for (int blk = 0; blk < 2; blk++) {
        int base = 1 + 13 * blk;
        wa.w[blk * 4 + 0] = (const float*)d_in[base + 2];
        wa.w[blk * 4 + 1] = (const float*)d_in[base + 5];
        wa.w[blk * 4 + 2] = (const float*)d_in[base + 9];
        wa.w[blk * 4 + 3] = (const float*)d_in[base + 11];
        __half* wb = wt + blk * 786432;
        wa.o[blk * 4 + 0] = wb;
        wa.o[blk * 4 + 1] = wb + 196608;
        wa.o[blk * 4 + 2] = wb + 262144;
        wa.o[blk * 4 + 3] = wb + 524288;
    }
    wt_all_kernel<<<1536, dim3(32, 8)>>>(wa);
    rpb_gather_kernel<<<16, 256>>>((const float*)d_in[1 + 4],
                                   (const float*)d_in[1 + 13 + 4], rbt);

    for (int blk = 0; blk < 2; blk++) {
        int base = 1 + 13 * blk;
        const float* n1g  = (const float*)d_in[base + 0];
        const float* n1b  = (const float*)d_in[base + 1];
        const float* qkvb = (const float*)d_in[base + 3];
        const float* pb   = (const float*)d_in[base + 6];
        const float* n2g  = (const float*)d_in[base + 7];
        const float* n2b  = (const float*)d_in[base + 8];
        const float* f1b  = (const float*)d_in[base + 10];
        const float* f2b  = (const float*)d_in[base + 12];

        __half* wb   = wt + blk * 786432;
        __half* qkvt = wb;
        __half* pwt  = wb + 196608;
        __half* f1t  = wb + 262144;
        __half* f2t  = wb + 524288;

        int shift  = blk ? 4 : 0;
        int masked = blk;
        int in16   = blk;   // block 0 reads fp32 x_in; block 1 reads fp16 x16

        // LN1 (+shift+partition)
        ln_kernel<<<8192, 256>>>(blk ? nullptr : x_in, x16,
                                 n1g, n1b, xw, shift, in16);
        // QKV
        h_gemm_kernel<<<dim3(6, 512), 256, GEMM_SMEM64>>>(
            xw, qkvt, qkvb, nullptr, qkv, 768, 256, 0, 1);
        // attention
        attn_tc_kernel<<<4096, 256>>>(qkv, rbt + blk * 8 * 225, attnb, masked);
        // proj
        h_gemm_kernel<<<dim3(2, 512), 256, GEMM_SMEM64>>>(
            attnb, pwt, pb, nullptr, proj, 256, 256, 0, 1);
        // rev + residual + LN2:  x16 = x_cur + rev(proj); h2 = LN(x16)
        rev_ln_kernel<<<8192, 256>>>(proj, blk ? nullptr : x_in, x16, x16,
                                     n2g, n2b, h2, shift, in16);
        // MLP1 + GELU
        h_gemm_kernel<<<dim3(8, 512), 256, GEMM_SMEM64>>>(
            h2, f1t, f1b, nullptr, mlp, 1024, 256, 1, 1);
        // MLP2 + residual: blk0 -> x16 (fp16), blk1 -> d_out (fp32)
        if (blk == 0)
            h_gemm_kernel<<<dim3(2, 512), 256, GEMM_SMEM64>>>(
                mlp, f2t, f2b, x16, x16, 256, 1024, 0, 1);
        else
            h_gemm_kernel<<<dim3(2, 512), 256, GEMM_SMEM64>>>(
                mlp, f2t, f2b, x16, x_out, 256, 1024, 0, 0);
    }
}